// round 13
// baseline (speedup 1.0000x reference)
#include <cuda_runtime.h>
#include <math.h>

// ---------------------------------------------------------------------------
// SMModel — factored GEMM on tensor cores (mma.sync.m16n8k8 tf32, 3xtf32).
// R12: x staged in smem as tf32 hi/lo pairs (1 cvt/elem, coalesced);
//      A fragments streamed via __ldg (no smem stage) -> 44KB smem, 2 blk/SM.
// ---------------------------------------------------------------------------

#define NC  8
#define HID 20

typedef unsigned long long ull;

__device__ __align__(16) float g_buf[5064832];

#define OFF_IMG1   0
#define OFF_IMG2   32768
#define OFF_X0A    40960
#define OFF_X0B    (OFF_X0A + 1048576)
#define OFF_X1A    (OFF_X0B + 1048576)
#define OFF_X1B    (OFF_X1A + 262144)
#define OFF_X2A    (OFF_X1B + 262144)
#define OFF_X2B    (OFF_X2A + 65536)
#define OFF_TABW5  (OFF_X2B + 65536)          // 13*129600
#define OFF_TABB   (OFF_TABW5 + 1684800)      // 13*5184
#define OFF_AFHI   (OFF_TABB + 67392)         // 13*14976
#define OFF_AFLO   (OFF_AFHI + 194688)        // 13*14976

__device__ __forceinline__ float elu_f(float v) {
    return v > 0.f ? v : (expf(v) - 1.f);
}
__device__ __forceinline__ unsigned tf32_of(float x) {
    unsigned u; asm("cvt.rna.tf32.f32 %0, %1;" : "=r"(u) : "f"(x)); return u;
}
__device__ __forceinline__ ull pk(float lo, float hi) {
    ull r; asm("mov.b64 %0, {%1, %2};" : "=l"(r) : "f"(lo), "f"(hi)); return r;
}
__device__ __forceinline__ void upk(ull v, float& lo, float& hi) {
    asm("mov.b64 {%0, %1}, %2;" : "=f"(lo), "=f"(hi) : "l"(v));
}
__device__ __forceinline__ void mma_tf32(float (&c)[4], const uint4& a,
                                         unsigned b0, unsigned b1) {
    asm volatile(
        "mma.sync.aligned.m16n8k8.row.col.f32.tf32.tf32.f32 "
        "{%0,%1,%2,%3}, {%4,%5,%6,%7}, {%8,%9}, {%0,%1,%2,%3};"
        : "+f"(c[0]), "+f"(c[1]), "+f"(c[2]), "+f"(c[3])
        : "r"(a.x), "r"(a.y), "r"(a.z), "r"(a.w), "r"(b0), "r"(b1));
}

// ---------------------------------------------------------------------------
// compose: effective 5x5 tables per (layer, cls, g, k).
// ---------------------------------------------------------------------------
__global__ void compose_kernel(
    const float* __restrict__ iW1, const float* __restrict__ ib1,
    const float* __restrict__ iW2, const float* __restrict__ ib2,
    const float* __restrict__ bW1, const float* __restrict__ bb1,
    const float* __restrict__ bW2, const float* __restrict__ bb2,
    float* __restrict__ tabW5, float* __restrict__ tabB)
{
    int idx = blockIdx.x * blockDim.x + threadIdx.x;
    if (idx >= 13 * 5184) return;
    int l = idx / 5184;
    int r0 = idx % 5184;
    int cls = r0 / 576;
    int g = (r0 % 576) / 9, k = r0 % 9;
    if (l == 0 && g >= 8) return;

    const float *W1, *b1, *W2, *b2;
    if (l == 0) { W1 = iW1; b1 = ib1; W2 = iW2; b2 = ib2; }
    else {
        int m = l - 1;
        W1 = bW1 + (size_t)m * 1280 * 9;  b1 = bb1 + (size_t)m * 1280;
        W2 = bW2 + (size_t)m * 576 * 180; b2 = bb2 + (size_t)m * 576;
    }

    float T[25];
#pragma unroll
    for (int j = 0; j < 25; j++) T[j] = 0.f;
    float bias = b2[g * 9 + k];

    for (int q = 0; q < 9; q++) {
        int qy = q / 3 - 1, qx = q % 3 - 1;
        bool vyl = (qy >= 0), vyh = (qy <= 0), vxl = (qx >= 0), vxh = (qx <= 0);
        bool in;
        switch (cls) {
            case 0: in = true; break;
            case 1: in = vyl; break;
            case 2: in = vyh; break;
            case 3: in = vxl; break;
            case 4: in = vxh; break;
            case 5: in = vyl && vxl; break;
            case 6: in = vyl && vxh; break;
            case 7: in = vyh && vxl; break;
            default: in = vyh && vxh; break;
        }
        if (!in) continue;
        for (int c = 0; c < HID; c++) {
            float w2 = W2[((size_t)(g * 9 + k) * HID + c) * 9 + q];
            bias += b1[g * HID + c] * w2;
#pragma unroll
            for (int r = 0; r < 9; r++) {
                int ry = r / 3 - 1, rx = r % 3 - 1;
                T[(qy + ry + 2) * 5 + (qx + rx + 2)] += w2 * W1[(size_t)(g * HID + c) * 9 + r];
            }
        }
    }

    float* To = tabW5 + (size_t)l * 129600 + ((size_t)(cls * 64 + g) * 9 + k) * 25;
#pragma unroll
    for (int j = 0; j < 25; j++) To[j] = T[j];
    tabB[(size_t)l * 5184 + (size_t)(cls * 64 + g) * 9 + k] = bias;
}

// ---------------------------------------------------------------------------
// vpack: fragment-ordered A matrices (hi + lo tf32) per layer.
// ---------------------------------------------------------------------------
__device__ __forceinline__ float vval(const float* __restrict__ tabW5,
                                      const float* __restrict__ tabB,
                                      int lyr, int nc, int r, int c)
{
    int i = c / 9, kk = c % 9;
    if (i >= nc) return 0.f;
    if (r < 200) {
        int d = r >> 3, o = r & 7;
        int g = (nc == 1) ? o : (o * 8 + i);
        return tabW5[(size_t)lyr * 129600 + ((size_t)g * 9 + kk) * 25 + d];
    }
    int o = r - 200;
    int g = (nc == 1) ? o : (o * 8 + i);
    return tabB[(size_t)lyr * 5184 + (size_t)g * 9 + kk];
}

__global__ void vpack_kernel(const float* __restrict__ tabW5,
                             const float* __restrict__ tabB,
                             float* __restrict__ afHi, float* __restrict__ afLo)
{
    int idx = blockIdx.x * blockDim.x + threadIdx.x;
    if (idx >= 13 * 13 * 9 * 32) return;
    int lyr = idx / (13 * 9 * 32);
    int rem = idx % (13 * 9 * 32);
    int m = rem / (9 * 32);
    int r2 = rem % (9 * 32);
    int ks = r2 / 32, lane = r2 % 32;
    int nc = (lyr == 0) ? 1 : 8;

    int rb = m * 16 + (lane >> 2);
    int cb = ks * 8 + (lane & 3);
    float v[4];
    v[0] = vval(tabW5, tabB, lyr, nc, rb,     cb);
    v[1] = vval(tabW5, tabB, lyr, nc, rb + 8, cb);
    v[2] = vval(tabW5, tabB, lyr, nc, rb,     cb + 4);
    v[3] = vval(tabW5, tabB, lyr, nc, rb + 8, cb + 4);

    size_t base = ((size_t)(lyr * 117 + m * 9 + ks) * 32 + lane) * 4;
#pragma unroll
    for (int q = 0; q < 4; q++) {
        unsigned hi = tf32_of(v[q]);
        float lof = v[q] - __uint_as_float(hi);
        afHi[base + q] = __uint_as_float(hi);
        afLo[base + q] = __uint_as_float(tf32_of(lof));
    }
}

// ---------------------------------------------------------------------------
// main TC kernel + fused scalar border. 256 thr. Tile = 32 wide x 16 tall.
// dynamic smem: simg 2880 + xs (8ch x 18x36 ull) 41472 = 44352 B -> 2 blk/SM.
// ---------------------------------------------------------------------------
__global__ __launch_bounds__(256) void smtc_kernel(
    const float* __restrict__ img0, const float* __restrict__ img1p, const float* __restrict__ img2p,
    const float* __restrict__ xin0, const float* __restrict__ xin1, const float* __restrict__ xin2,
    float* __restrict__ out0, float* __restrict__ out1, float* __restrict__ out2,
    const float* __restrict__ afHi, const float* __restrict__ afLo,
    const float* __restrict__ tabW5, const float* __restrict__ tabB,
    int nc_in, int slotBase, int mode)
{
    const int bx = blockIdx.x;
    const int b = blockIdx.z;
    const int tid = threadIdx.x;
    const int mainX = (mode == 0) ? 32 : 42;

    if (bx >= mainX) {
        // ---------------- scalar border path (exact, cls tables) ----------
        int bp = (bx - mainX) * 256 + tid;
        int limit = (mode == 0) ? 508 : 884;
        if (bp >= limit) return;
        int s, e;
        if (bp < 508)      { s = 0; e = bp; }
        else if (bp < 760) { s = 1; e = bp - 508; }
        else               { s = 2; e = bp - 760; }
        const float* img = (s == 0) ? img0 : (s == 1) ? img1p : img2p;
        const float* xin = (s == 0) ? xin0 : (s == 1) ? xin1 : xin2;
        float* out = (s == 0) ? out0 : (s == 1) ? out1 : out2;
        const int N = 128 >> s;
        const int slot = slotBase + s;

        int py, px;
        if (e < N)              { py = 0;     px = e; }
        else if (e < 2 * N)     { py = N - 1; px = e - N; }
        else if (e < 3 * N - 2) { py = e - 2 * N + 1;       px = 0; }
        else                    { py = e - (3 * N - 2) + 1; px = N - 1; }

        bool Tt = (py == 0), Bb = (py == N - 1), Ll = (px == 0), Rr = (px == N - 1);
        int cls = Tt ? (Ll ? 5 : (Rr ? 6 : 1))
                     : (Bb ? (Ll ? 7 : (Rr ? 8 : 2)) : (Ll ? 3 : 4));

        float w[25];
        const float* ibp = img + (size_t)b * N * N;
#pragma unroll
        for (int dy = 0; dy < 5; dy++)
#pragma unroll
            for (int dx = 0; dx < 5; dx++) {
                int iy = py - 2 + dy, ix = px - 2 + dx;
                w[dy * 5 + dx] = (iy >= 0 && iy < N && ix >= 0 && ix < N) ? ibp[iy * N + ix] : 0.f;
            }

        for (int o = 0; o < NC; o++) {
            float accv = 0.f;
            for (int i = 0; i < nc_in; i++) {
                int g = (nc_in == 1) ? o : (o * 8 + i);
                const float* tb = tabW5 + (size_t)slot * 129600 + ((size_t)(cls * 64 + g) * 9) * 25;
                const float* bb = tabB + (size_t)slot * 5184 + (size_t)(cls * 64 + g) * 9;
                const float* xb = xin + ((size_t)b * nc_in + i) * N * N;
                float Kf[9];
#pragma unroll
                for (int k = 0; k < 9; k++) Kf[k] = bb[k];
#pragma unroll
                for (int j = 0; j < 25; j++) {
                    float v = w[j];
#pragma unroll
                    for (int k = 0; k < 9; k++) Kf[k] += tb[k * 25 + j] * v;
                }
#pragma unroll
                for (int k = 0; k < 9; k++) {
                    int yy = py + k / 3 - 1, xx = px + k % 3 - 1;
                    float xv = (yy >= 0 && yy < N && xx >= 0 && xx < N) ? xb[yy * N + xx] : 0.f;
                    accv += Kf[k] * xv;
                }
            }
            out[((size_t)b * NC + o) * N * N + py * N + px] = elu_f(accv);
        }
        return;
    }

    // ---------------- main tensor-core path ----------------
    extern __shared__ __align__(16) char smraw[];
    float* simg = (float*)smraw;                 // 720 f = 2880 B
    ull*   xs   = (ull*)(smraw + 2880);          // nc*648 ull (<= 41472 B)

    int s, tile;
    const float *img, *xin;
    float* out;
    if (mode == 0)    { s = 0; tile = bx; img = img0; xin = xin0; out = out0; }
    else if (bx < 32) { s = 0; tile = bx;      img = img0;  xin = xin0; out = out0; }
    else if (bx < 40) { s = 1; tile = bx - 32; img = img1p; xin = xin1; out = out1; }
    else              { s = 2; tile = bx - 40; img = img2p; xin = xin2; out = out2; }
    const int N = 128 >> s;
    const int tilesX = N / 32;
    const int tx0 = (tile % tilesX) * 32;
    const int ty0 = (tile / tilesX) * 16;
    const int slot = slotBase + s;

    // stage image tile (halo 2, zero-padded)
    const float* ib = img + (size_t)b * N * N;
    for (int i = tid; i < 720; i += 256) {
        int ly = i / 36, lx = i % 36;
        int gy = ty0 - 2 + ly, gx = tx0 - 2 + lx;
        simg[i] = (gy >= 0 && gy < N && gx >= 0 && gx < N) ? ib[gy * N + gx] : 0.f;
    }
    // stage x tiles as (tf32hi, tf32lo) pairs: rows ty0-1..ty0+16, cols tx0-1..tx0+32
    for (int i = tid; i < nc_in * 612; i += 256) {
        int ii = i / 612, r = (i % 612) / 34, c = i % 34;
        int gy = ty0 - 1 + r, gx = tx0 - 1 + c;
        float xv = 0.f;
        if (gy >= 0 && gy < N && gx >= 0 && gx < N)
            xv = xin[((size_t)(b * nc_in + ii) * N + gy) * N + gx];
        unsigned hi = tf32_of(xv);
        float lof = xv - __uint_as_float(hi);
        xs[ii * 648 + r * 36 + c] = pk(__uint_as_float(hi),
                                       __uint_as_float(tf32_of(lof)));
    }
    __syncthreads();

    const int warp = tid >> 5, lane = tid & 31;
    const int lq = lane >> 2, lr = lane & 3;
    const int ksmax = (nc_in == 1) ? 2 : 9;
    const uint4* aH = (const uint4*)afHi + (size_t)slot * 3744;
    const uint4* aL = (const uint4*)afLo + (size_t)slot * 3744;

#pragma unroll 1
    for (int g = 0; g < 4; g++) {
        const int gg = warp * 4 + g;

        // ---- gather B fragments from smem (packed hi/lo) ----
        ull bxr[2][9][2];
#pragma unroll
        for (int ks = 0; ks < 9; ks++) {
#pragma unroll
            for (int h = 0; h < 2; h++) {
                int krow = ks * 8 + lr + h * 4;
                int ii = krow / 9;
                int kk = krow - ii * 9;
                int ky = kk / 3, kx = kk - ky * 3;    // 0..2 (offset+1)
#pragma unroll
                for (int j = 0; j < 2; j++) {
                    int pB = gg * 16 + j * 8 + lq;
                    int row = (pB >> 5) + ky;
                    int col = (pB & 31) + kx;
                    bxr[j][ks][h] = (ii < nc_in) ? xs[ii * 648 + row * 36 + col] : 0ull;
                }
            }
        }

        float outv[2][2] = {{0.f, 0.f}, {0.f, 0.f}};

#pragma unroll
        for (int m = 0; m < 13; m++) {
            float c[2][4] = {{0.f,0.f,0.f,0.f},{0.f,0.f,0.f,0.f}};
#pragma unroll
            for (int ks = 0; ks < 9; ks++) {
                if (ks >= ksmax) continue;
                const uint4 Ah = __ldg(aH + (m * 9 + ks) * 32 + lane);
                const uint4 Al = __ldg(aL + (m * 9 + ks) * 32 + lane);
#pragma unroll
                for (int j = 0; j < 2; j++) {
                    float h0, l0, h1, l1;
                    upk(bxr[j][ks][0], h0, l0);
                    upk(bxr[j][ks][1], h1, l1);
                    unsigned bh0 = __float_as_uint(h0), bh1 = __float_as_uint(h1);
                    unsigned bl0 = __float_as_uint(l0), bl1 = __float_as_uint(l1);
                    mma_tf32(c[j], Ah, bh0, bh1);
                    mma_tf32(c[j], Ah, bl0, bl1);
                    mma_tf32(c[j], Al, bh0, bh1);
                }
            }
            // ---- register epilogue for this m-tile ----
            const int d0 = 2 * m, d1 = 2 * m + 1;
            const int dy0 = d0 / 5 - 2, dx0 = d0 % 5 - 2;
            const int dy1 = d1 / 5 - 2, dx1 = d1 % 5 - 2;
#pragma unroll
            for (int j = 0; j < 2; j++) {
                int pp = gg * 16 + j * 8 + lr * 2;
                int pyr = (pp >> 5) + 2, pxc = (pp & 31) + 2;
                float w00 = simg[(pyr + dy0) * 36 + pxc + dx0];
                float w01 = simg[(pyr + dy0) * 36 + pxc + 1 + dx0];
                float w10, w11;
                if (m < 12) {
                    w10 = simg[(pyr + dy1) * 36 + pxc + dx1];
                    w11 = simg[(pyr + dy1) * 36 + pxc + 1 + dx1];
                } else {
                    w10 = 1.f; w11 = 1.f;
                }
                outv[j][0] += w00 * c[j][0] + w10 * c[j][2];
                outv[j][1] += w01 * c[j][1] + w11 * c[j][3];
            }
        }

        // ---- store (interior only; o = lane/4) ----
#pragma unroll
        for (int j = 0; j < 2; j++) {
            int pp = gg * 16 + j * 8 + lr * 2;
            int gy = ty0 + (pp >> 5), gx = tx0 + (pp & 31);
            if (gy > 0 && gy < N - 1) {
                float* ob = out + ((size_t)(b * NC + lq) * N + gy) * N;
                if (gx > 0 && gx < N - 1)         ob[gx]     = elu_f(outv[j][0]);
                if (gx + 1 > 0 && gx + 1 < N - 1) ob[gx + 1] = elu_f(outv[j][1]);
            }
        }
    }
}

// ---------------------------------------------------------------------------
__global__ void down_kernel(const float* __restrict__ in, float* __restrict__ out,
                            int C, int No)
{
    int idx = blockIdx.x * blockDim.x + threadIdx.x;
    int total = C * No * No;
    if (idx >= total) return;
    int c = idx / (No * No);
    int p = idx % (No * No);
    int h = p / No, w = p % No;
    int Ni = No * 2;
    const float* ib = in + (size_t)c * Ni * Ni;
    float sv = ib[(2 * h) * Ni + 2 * w] + ib[(2 * h) * Ni + 2 * w + 1]
             + ib[(2 * h + 1) * Ni + 2 * w] + ib[(2 * h + 1) * Ni + 2 * w + 1];
    out[idx] = 0.25f * sv;
}

__global__ void combine_kernel(const float* __restrict__ x0,
                               const float* __restrict__ x1,
                               const float* __restrict__ x2,
                               const float* __restrict__ w5, const float* __restrict__ b5,
                               const float* __restrict__ w6, const float* __restrict__ b6,
                               float* __restrict__ out)
{
    int idx = blockIdx.x * blockDim.x + threadIdx.x;
    if (idx >= 8 * 128 * 128) return;
    int b = idx / (128 * 128);
    int p = idx % (128 * 128);
    int h = p / 128, w = p % 128;
    float v[NC];
#pragma unroll
    for (int c = 0; c < NC; c++) {
        v[c] = x0[((size_t)b * NC + c) * 16384 + p]
             + x1[((size_t)b * NC + c) * 4096 + (h >> 1) * 64 + (w >> 1)]
             + x2[((size_t)b * NC + c) * 1024 + (h >> 2) * 32 + (w >> 2)];
    }
    float accv = b6[0];
#pragma unroll
    for (int o = 0; o < NC; o++) {
        float y = b5[o];
#pragma unroll
        for (int c = 0; c < NC; c++) y += w5[o * NC + c] * v[c];
        y = elu_f(y);
        accv += w6[o] * y;
    }
    out[idx] = accv;
}

// ---------------------------------------------------------------------------
extern "C" void kernel_launch(void* const* d_in, const int* in_sizes, int n_in,
                              void* d_out, int out_size)
{
    const float* image = (const float*)d_in[0];
    const float* x_in  = (const float*)d_in[1];
    const float* iW1   = (const float*)d_in[2];
    const float* ib1   = (const float*)d_in[3];
    const float* iW2   = (const float*)d_in[4];
    const float* ib2   = (const float*)d_in[5];
    const float* bW1   = (const float*)d_in[6];
    const float* bb1   = (const float*)d_in[7];
    const float* bW2   = (const float*)d_in[8];
    const float* bb2   = (const float*)d_in[9];
    const float* w5    = (const float*)d_in[10];
    const float* b5    = (const float*)d_in[11];
    const float* w6    = (const float*)d_in[12];
    const float* b6    = (const float*)d_in[13];

    float* base;
    cudaGetSymbolAddress((void**)&base, g_buf);
    float* img1  = base + OFF_IMG1;
    float* img2  = base + OFF_IMG2;
    float* x0a   = base + OFF_X0A;
    float* x0b   = base + OFF_X0B;
    float* x1a   = base + OFF_X1A;
    float* x1b   = base + OFF_X1B;
    float* x2a   = base + OFF_X2A;
    float* x2b   = base + OFF_X2B;
    float* tabW5 = base + OFF_TABW5;
    float* tabB  = base + OFF_TABB;
    float* afHi  = base + OFF_AFHI;
    float* afLo  = base + OFF_AFLO;

    static int smem_set = 0;
    const int SMEM = 44352;
    if (!smem_set) {
        cudaFuncSetAttribute(smtc_kernel,
                             cudaFuncAttributeMaxDynamicSharedMemorySize, SMEM);
        smem_set = 1;
    }

    // tables + fragment pack, all layers upfront (x-independent)
    compose_kernel<<<(13 * 5184 + 127) / 128, 128>>>(
        iW1, ib1, iW2, ib2, bW1, bb1, bW2, bb2, tabW5, tabB);
    vpack_kernel<<<(13 * 13 * 9 * 32 + 127) / 128, 128>>>(tabW5, tabB, afHi, afLo);

    // image pyramid
    down_kernel<<<(8 * 64 * 64 + 255) / 256, 256>>>(image, img1, 8, 64);
    down_kernel<<<(8 * 32 * 32 + 255) / 256, 256>>>(img1, img2, 8, 32);

    // init block (slot 0, nc_in=1, full-res only): 32 main + 2 border
    smtc_kernel<<<dim3(34, 1, 8), 256, SMEM>>>(image, img1, img2,
        x_in, x_in, x_in, x0a, x0a, x0a, afHi, afLo, tabW5, tabB, 1, 0, 0);

    // downsample x
    down_kernel<<<(64 * 64 * 64 + 255) / 256, 256>>>(x0a, x1a, 64, 64);
    down_kernel<<<(64 * 32 * 32 + 255) / 256, 256>>>(x1a, x2a, 64, 32);

    float *xc = x0a, *xn = x0b;
    float *x1c = x1a, *x1n = x1b;
    float *x2c = x2a, *x2n = x2b;

    for (int t = 0; t < 4; t++) {
        // 42 main (32 full + 8 mid + 2 small) + 4 border
        smtc_kernel<<<dim3(46, 1, 8), 256, SMEM>>>(image, img1, img2,
            xc, x1c, x2c, xn, x1n, x2n, afHi, afLo, tabW5, tabB,
            8, 1 + 3 * t, 1);
        { float* tp = xc;  xc = xn;   xn = tp; }
        { float* tp = x1c; x1c = x1n; x1n = tp; }
        { float* tp = x2c; x2c = x2n; x2n = tp; }
    }

    combine_kernel<<<(8 * 128 * 128 + 255) / 256, 256>>>(
        xc, x1c, x2c, w5, b5, w6, b6, (float*)d_out);
}

// round 14
// speedup vs baseline: 1.4831x; 1.4831x over previous
#include <cuda_runtime.h>
#include <math.h>

// ---------------------------------------------------------------------------
// SMModel — composed-5x5, packed f32x2 (re-anchored 771us config).
// Only delta vs best-known: spair built directly from gmem (no simg stage,
// one fewer barrier, ~2.5K fewer smem ops per block).
// ---------------------------------------------------------------------------

#define NC    8
#define HID   20
#define CHG   4

typedef unsigned long long ull;

__device__ __align__(16) float g_buf[5064832];

__device__ __forceinline__ float elu_f(float v) {
    return v > 0.f ? v : (expf(v) - 1.f);
}
__device__ __forceinline__ ull pk(float lo, float hi) {
    ull r; asm("mov.b64 %0, {%1, %2};" : "=l"(r) : "f"(lo), "f"(hi)); return r;
}
__device__ __forceinline__ void upk(ull v, float& lo, float& hi) {
    asm("mov.b64 {%0, %1}, %2;" : "=f"(lo), "=f"(hi) : "l"(v));
}
__device__ __forceinline__ ull fma2(ull a, ull b, ull c) {
    ull d; asm("fma.rn.f32x2 %0, %1, %2, %3;" : "=l"(d) : "l"(a), "l"(b), "l"(c)); return d;
}

// ---------------------------------------------------------------------------
// compose: ALL 13 layers, one launch.
// tabW5[l][cls9][64][9][25] f, tabB[l][cls9][64][9] f,
// tabDup[l][64][25*12] ull (cls0 pairs, slot d*12+kg*4+j), tabBDup[l][64][12].
// ---------------------------------------------------------------------------
__global__ void compose_kernel(
    const float* __restrict__ iW1, const float* __restrict__ ib1,
    const float* __restrict__ iW2, const float* __restrict__ ib2,
    const float* __restrict__ bW1, const float* __restrict__ bb1,
    const float* __restrict__ bW2, const float* __restrict__ bb2,
    float* __restrict__ tabW5, float* __restrict__ tabB,
    ull* __restrict__ tabDup, ull* __restrict__ tabBDup)
{
    int idx = blockIdx.x * blockDim.x + threadIdx.x;
    if (idx >= 13 * 5184) return;
    int l = idx / 5184;
    int r0 = idx % 5184;
    int cls = r0 / 576;
    int g = (r0 % 576) / 9, k = r0 % 9;
    if (l == 0 && g >= 8) return;

    const float *W1, *b1, *W2, *b2;
    if (l == 0) { W1 = iW1; b1 = ib1; W2 = iW2; b2 = ib2; }
    else {
        int m = l - 1;
        W1 = bW1 + (size_t)m * 1280 * 9;  b1 = bb1 + (size_t)m * 1280;
        W2 = bW2 + (size_t)m * 576 * 180; b2 = bb2 + (size_t)m * 576;
    }

    float T[25];
#pragma unroll
    for (int j = 0; j < 25; j++) T[j] = 0.f;
    float bias = b2[g * 9 + k];

    for (int q = 0; q < 9; q++) {
        int qy = q / 3 - 1, qx = q % 3 - 1;
        bool vyl = (qy >= 0), vyh = (qy <= 0), vxl = (qx >= 0), vxh = (qx <= 0);
        bool in;
        switch (cls) {
            case 0: in = true; break;
            case 1: in = vyl; break;
            case 2: in = vyh; break;
            case 3: in = vxl; break;
            case 4: in = vxh; break;
            case 5: in = vyl && vxl; break;
            case 6: in = vyl && vxh; break;
            case 7: in = vyh && vxl; break;
            default: in = vyh && vxh; break;
        }
        if (!in) continue;
        for (int c = 0; c < HID; c++) {
            float w2 = W2[((size_t)(g * 9 + k) * HID + c) * 9 + q];
            bias += b1[g * HID + c] * w2;
#pragma unroll
            for (int r = 0; r < 9; r++) {
                int ry = r / 3 - 1, rx = r % 3 - 1;
                T[(qy + ry + 2) * 5 + (qx + rx + 2)] += w2 * W1[(size_t)(g * HID + c) * 9 + r];
            }
        }
    }

    float* To = tabW5 + (size_t)l * 129600 + ((size_t)(cls * 64 + g) * 9 + k) * 25;
#pragma unroll
    for (int j = 0; j < 25; j++) To[j] = T[j];
    tabB[(size_t)l * 5184 + (size_t)(cls * 64 + g) * 9 + k] = bias;

    if (cls == 0) {
        ull* dd = tabDup + (size_t)l * 19200 + (size_t)g * 300;
        int kg = k / 3, j = k % 3;
#pragma unroll
        for (int d = 0; d < 25; d++) dd[d * 12 + kg * 4 + j] = pk(T[d], T[d]);
        tabBDup[(size_t)l * 768 + g * 12 + kg * 4 + j] = pk(bias, bias);
    }
}

// ---------------------------------------------------------------------------
__device__ __forceinline__ void load_row(const ull* __restrict__ spair,
                                         int row, int pqx, ull (&R)[7])
{
    const ull* base = spair + row * 36 + pqx;
    ulonglong2 t0 = *reinterpret_cast<const ulonglong2*>(base);
    ulonglong2 t1 = *reinterpret_cast<const ulonglong2*>(base + 2);
    ulonglong2 t2 = *reinterpret_cast<const ulonglong2*>(base + 4);
    R[0] = t0.x; R[1] = t0.y; R[2] = t1.x; R[3] = t1.y;
    R[4] = t2.x; R[5] = t2.y; R[6] = base[6];
}

// one dy row-step: 5 dx x 3 j x 4 acc (weights per-dx inline, as in 771us)
__device__ __forceinline__ void conv_step(const ull* __restrict__ wrow,
                                          const ull (&R)[7], const ull (&S)[7],
                                          ull (&acc)[3][2][2])
{
#pragma unroll
    for (int dx = 0; dx < 5; dx++) {
        const ull* wp = wrow + dx * 12;
        ulonglong2 t = *reinterpret_cast<const ulonglong2*>(wp);
        ull w0 = t.x, w1 = t.y, w2 = wp[2];
        acc[0][0][0] = fma2(R[dx],     w0, acc[0][0][0]);
        acc[0][0][1] = fma2(R[dx + 2], w0, acc[0][0][1]);
        acc[0][1][0] = fma2(S[dx],     w0, acc[0][1][0]);
        acc[0][1][1] = fma2(S[dx + 2], w0, acc[0][1][1]);
        acc[1][0][0] = fma2(R[dx],     w1, acc[1][0][0]);
        acc[1][0][1] = fma2(R[dx + 2], w1, acc[1][0][1]);
        acc[1][1][0] = fma2(S[dx],     w1, acc[1][1][0]);
        acc[1][1][1] = fma2(S[dx + 2], w1, acc[1][1][1]);
        acc[2][0][0] = fma2(R[dx],     w2, acc[2][0][0]);
        acc[2][0][1] = fma2(R[dx + 2], w2, acc[2][0][1]);
        acc[2][1][0] = fma2(S[dx],     w2, acc[2][1][0]);
        acc[2][1][1] = fma2(S[dx + 2], w2, acc[2][1][1]);
    }
}

// ---------------------------------------------------------------------------
// main + border fused. 128 threads/block, thread = 2 rows x 4 cols.
// ---------------------------------------------------------------------------
__global__ __launch_bounds__(128) void smmain_kernel(
    const float* __restrict__ img0, const float* __restrict__ img1p, const float* __restrict__ img2p,
    const float* __restrict__ xin0, const float* __restrict__ xin1, const float* __restrict__ xin2,
    float* __restrict__ out0, float* __restrict__ out1, float* __restrict__ out2,
    const ull* __restrict__ tabDup, const ull* __restrict__ tabBDup,
    const float* __restrict__ tabW5, const float* __restrict__ tabB,
    int nc_in, int slotBase, int mode)
{
    const int bx = blockIdx.x;
    const int o = blockIdx.y, b = blockIdx.z;
    const int tid = threadIdx.x;
    const int mainX = (mode == 0) ? 16 : 21;

    if (bx >= mainX) {
        // ---------------- border path ----------------
        int bp = (bx - mainX) * 128 + tid;
        int limit = (mode == 0) ? 508 : 884;
        if (bp >= limit) return;
        int s, e;
        if (bp < 508)      { s = 0; e = bp; }
        else if (bp < 760) { s = 1; e = bp - 508; }
        else               { s = 2; e = bp - 760; }
        const float* img = (s == 0) ? img0 : (s == 1) ? img1p : img2p;
        const float* xin = (s == 0) ? xin0 : (s == 1) ? xin1 : xin2;
        float* out = (s == 0) ? out0 : (s == 1) ? out1 : out2;
        const int N = 128 >> s;
        const int slot = slotBase + s;

        int py, px;
        if (e < N)              { py = 0;     px = e; }
        else if (e < 2 * N)     { py = N - 1; px = e - N; }
        else if (e < 3 * N - 2) { py = e - 2 * N + 1;       px = 0; }
        else                    { py = e - (3 * N - 2) + 1; px = N - 1; }

        bool Tt = (py == 0), Bb = (py == N - 1), Ll = (px == 0), Rr = (px == N - 1);
        int cls = Tt ? (Ll ? 5 : (Rr ? 6 : 1))
                     : (Bb ? (Ll ? 7 : (Rr ? 8 : 2)) : (Ll ? 3 : 4));

        float w[25];
        const float* ibp = img + (size_t)b * N * N;
#pragma unroll
        for (int dy = 0; dy < 5; dy++)
#pragma unroll
            for (int dx = 0; dx < 5; dx++) {
                int iy = py - 2 + dy, ix = px - 2 + dx;
                w[dy * 5 + dx] = (iy >= 0 && iy < N && ix >= 0 && ix < N) ? ibp[iy * N + ix] : 0.f;
            }

        float accv = 0.f;
        for (int i = 0; i < nc_in; i++) {
            int g = o * nc_in + i;
            const float* tb = tabW5 + (size_t)slot * 129600 + ((size_t)(cls * 64 + g) * 9) * 25;
            const float* bb = tabB + (size_t)slot * 5184 + (size_t)(cls * 64 + g) * 9;
            const float* xb = xin + ((size_t)b * nc_in + i) * N * N;
            float Kf[9];
#pragma unroll
            for (int k = 0; k < 9; k++) Kf[k] = bb[k];
#pragma unroll
            for (int j = 0; j < 25; j++) {
                float v = w[j];
#pragma unroll
                for (int k = 0; k < 9; k++) Kf[k] += tb[k * 25 + j] * v;
            }
#pragma unroll
            for (int k = 0; k < 9; k++) {
                int yy = py + k / 3 - 1, xx = px + k % 3 - 1;
                float xv = (yy >= 0 && yy < N && xx >= 0 && xx < N) ? xb[yy * N + xx] : 0.f;
                accv += Kf[k] * xv;
            }
        }
        out[((size_t)b * NC + o) * N * N + py * N + px] = elu_f(accv);
        return;
    }

    // ---------------- main (interior) path ----------------
    __shared__ __align__(16) ull   spair[36 * 36];         // 10368 B
    __shared__ __align__(16) float sxs[CHG * 34 * 36];     // 19584 B
    __shared__ __align__(16) ull   sWd[CHG * 300];         // 9600 B
    __shared__ __align__(16) ull   sBd[CHG * 12];          // 384 B

    int s, tile;
    const float *img, *xin;
    float* out;
    if (bx < 16)      { s = 0; tile = bx;      img = img0;  xin = xin0; out = out0; }
    else if (bx < 20) { s = 1; tile = bx - 16; img = img1p; xin = xin1; out = out1; }
    else              { s = 2; tile = bx - 20; img = img2p; xin = xin2; out = out2; }
    const int N = 128 >> s;
    const int tilesX = N / 32;
    const int tx0 = (tile % tilesX) * 32, ty0 = (tile / tilesX) * 32;
    const int slot = slotBase + s;
    const int pqx = (tid & 7) * 4;
    const int pqy = (tid >> 3) * 2;

    // packed adjacent-pair image tile, built straight from gmem (zero-padded)
    const float* ib = img + (size_t)b * N * N;
    for (int idx = tid; idx < 36 * 35; idx += 128) {
        int ly = idx / 35, lx = idx % 35;
        int gy = ty0 - 2 + ly, gx = tx0 - 2 + lx;
        bool iny = (gy >= 0 && gy < N);
        float v0 = (iny && gx >= 0 && gx < N) ? ib[gy * N + gx] : 0.f;
        float v1 = (iny && gx + 1 >= 0 && gx + 1 < N) ? ib[gy * N + gx + 1] : 0.f;
        spair[ly * 36 + lx] = pk(v0, v1);
    }
    // (sync before compute provided by the per-phase post-load barrier)

    ull oacc[2][2];
    oacc[0][0] = 0ull; oacc[0][1] = 0ull; oacc[1][0] = 0ull; oacc[1][1] = 0ull;

    for (int i0 = 0; i0 < nc_in; i0 += CHG) {
        const int chg = (nc_in - i0 < CHG) ? (nc_in - i0) : CHG;
        __syncthreads();   // previous phase compute done (and spair build, phase 0)

        // stage chg channels: x tiles, weights, biases
        for (int idx = tid; idx < chg * 1156; idx += 128) {
            int ci = idx / 1156, r = idx % 1156;
            int ly = r / 34, lx = r % 34;
            int gy = ty0 - 1 + ly, gx = tx0 - 1 + lx;
            const float* xb = xin + ((size_t)b * nc_in + (i0 + ci)) * N * N;
            sxs[ci * 1224 + ly * 36 + lx] =
                (gy >= 0 && gy < N && gx >= 0 && gx < N) ? xb[gy * N + gx] : 0.f;
        }
        for (int idx = tid; idx < chg * 300; idx += 128) {
            int ci = idx / 300, j = idx % 300;
            int g = o * nc_in + i0 + ci;
            sWd[ci * 300 + j] = tabDup[(size_t)slot * 19200 + (size_t)g * 300 + j];
        }
        if (tid < chg * 12) {
            int ci = tid / 12, j = tid % 12;
            int g = o * nc_in + i0 + ci;
            sBd[ci * 12 + j] = tabBDup[(size_t)slot * 768 + (size_t)g * 12 + j];
        }
        __syncthreads();

#pragma unroll 1
        for (int ci = 0; ci < chg; ci++) {
            const ull*   wd = sWd + ci * 300;
            const ull*   bd = sBd + ci * 12;
            const float* xc = sxs + ci * 1224;

#pragma unroll 1
            for (int kg = 0; kg < 3; kg++) {
                ull acc[3][2][2];
#pragma unroll
                for (int j = 0; j < 3; j++) {
                    ull bb = bd[kg * 4 + j];
                    acc[j][0][0] = bb; acc[j][0][1] = bb;
                    acc[j][1][0] = bb; acc[j][1][1] = bb;
                }

                const ull* wk = wd + kg * 4;
                ull A[7], B[7];
                load_row(spair, pqy,     pqx, A);
                load_row(spair, pqy + 1, pqx, B);
                conv_step(wk,          A, B, acc);
                load_row(spair, pqy + 2, pqx, A);
                conv_step(wk + 60,     B, A, acc);
                load_row(spair, pqy + 3, pqx, B);
                conv_step(wk + 120,    A, B, acc);
                load_row(spair, pqy + 4, pqx, A);
                conv_step(wk + 180,    B, A, acc);
                load_row(spair, pqy + 5, pqx, B);
                conv_step(wk + 240,    A, B, acc);

                // apply: load x pairs only now (short live range)
#pragma unroll
                for (int rr = 0; rr < 2; rr++) {
                    const float* xr = xc + (pqy + kg + rr) * 36 + pqx;
                    float4 q4 = *reinterpret_cast<const float4*>(xr);
                    float2 q2 = *reinterpret_cast<const float2*>(xr + 4);
                    ull x0 = pk(q4.x, q4.y), x1 = pk(q4.y, q4.z), x2 = pk(q4.z, q4.w);
                    ull x3 = pk(q4.w, q2.x), x4 = pk(q2.x, q2.y);
                    oacc[rr][0] = fma2(acc[0][rr][0], x0, oacc[rr][0]);
                    oacc[rr][1] = fma2(acc[0][rr][1], x2, oacc[rr][1]);
                    oacc[rr][0] = fma2(acc[1][rr][0], x1, oacc[rr][0]);
                    oacc[rr][1] = fma2(acc[1][rr][1], x3, oacc[rr][1]);
                    oacc[rr][0] = fma2(acc[2][rr][0], x2, oacc[rr][0]);
                    oacc[rr][1] = fma2(acc[2][rr][1], x4, oacc[rr][1]);
                }
            }
        }
    }

    float* ob = out + ((size_t)b * NC + o) * N * N;
#pragma unroll
    for (int sy = 0; sy < 2; sy++) {
#pragma unroll
        for (int cp = 0; cp < 2; cp++) {
            float lo, hi;
            upk(oacc[sy][cp], lo, hi);
            int row = ty0 + pqy + sy, col = tx0 + pqx + 2 * cp;
            if (row > 0 && row < N - 1) {
                if (col > 0 && col < N - 1)         ob[row * N + col]     = elu_f(lo);
                if (col + 1 > 0 && col + 1 < N - 1) ob[row * N + col + 1] = elu_f(hi);
            }
        }
    }
}

// ---------------------------------------------------------------------------
__global__ void down_kernel(const float* __restrict__ in, float* __restrict__ out,
                            int C, int No)
{
    int idx = blockIdx.x * blockDim.x + threadIdx.x;
    int total = C * No * No;
    if (idx >= total) return;
    int c = idx / (No * No);
    int p = idx % (No * No);
    int h = p / No, w = p % No;
    int Ni = No * 2;
    const float* ib = in + (size_t)c * Ni * Ni;
    float sv = ib[(2 * h) * Ni + 2 * w] + ib[(2 * h) * Ni + 2 * w + 1]
             + ib[(2 * h + 1) * Ni + 2 * w] + ib[(2 * h + 1) * Ni + 2 * w + 1];
    out[idx] = 0.25f * sv;
}

__global__ void combine_kernel(const float* __restrict__ x0,
                               const float* __restrict__ x1,
                               const float* __restrict__ x2,
                               const float* __restrict__ w5, const float* __restrict__ b5,
                               const float* __restrict__ w6, const float* __restrict__ b6,
                               float* __restrict__ out)
{
    int idx = blockIdx.x * blockDim.x + threadIdx.x;
    if (idx >= 8 * 128 * 128) return;
    int b = idx / (128 * 128);
    int p = idx % (128 * 128);
    int h = p / 128, w = p % 128;
    float v[NC];
#pragma unroll
    for (int c = 0; c < NC; c++) {
        v[c] = x0[((size_t)b * NC + c) * 16384 + p]
             + x1[((size_t)b * NC + c) * 4096 + (h >> 1) * 64 + (w >> 1)]
             + x2[((size_t)b * NC + c) * 1024 + (h >> 2) * 32 + (w >> 2)];
    }
    float accv = b6[0];
#pragma unroll
    for (int o = 0; o < NC; o++) {
        float y = b5[o];
#pragma unroll
        for (int c = 0; c < NC; c++) y += w5[o * NC + c] * v[c];
        y = elu_f(y);
        accv += w6[o] * y;
    }
    out[idx] = accv;
}

// ---------------------------------------------------------------------------
extern "C" void kernel_launch(void* const* d_in, const int* in_sizes, int n_in,
                              void* d_out, int out_size)
{
    const float* image = (const float*)d_in[0];
    const float* x_in  = (const float*)d_in[1];
    const float* iW1   = (const float*)d_in[2];
    const float* ib1   = (const float*)d_in[3];
    const float* iW2   = (const float*)d_in[4];
    const float* ib2   = (const float*)d_in[5];
    const float* bW1   = (const float*)d_in[6];
    const float* bb1   = (const float*)d_in[7];
    const float* bW2   = (const float*)d_in[8];
    const float* bb2   = (const float*)d_in[9];
    const float* w5    = (const float*)d_in[10];
    const float* b5    = (const float*)d_in[11];
    const float* w6    = (const float*)d_in[12];
    const float* b6    = (const float*)d_in[13];

    float* base;
    cudaGetSymbolAddress((void**)&base, g_buf);
    float* img1 = base;
    float* img2 = img1 + 32768;
    float* x0a  = img2 + 8192;
    float* x0b  = x0a + 1048576;
    float* x1a  = x0b + 1048576;
    float* x1b  = x1a + 262144;
    float* x2a  = x1b + 262144;
    float* x2b  = x2a + 65536;
    float* tabW5 = x2b + 65536;                // 13*129600
    float* tabB  = tabW5 + 13 * 129600;        // 13*5184
    ull*   tabDup  = (ull*)(tabB + 13 * 5184); // 13*19200 ull
    ull*   tabBDup = tabDup + 13 * 19200;      // 13*768 ull

    // all tables upfront (x-independent)
    compose_kernel<<<(13 * 5184 + 127) / 128, 128>>>(
        iW1, ib1, iW2, ib2, bW1, bb1, bW2, bb2, tabW5, tabB, tabDup, tabBDup);

    // image pyramid
    down_kernel<<<(8 * 64 * 64 + 255) / 256, 256>>>(image, img1, 8, 64);
    down_kernel<<<(8 * 32 * 32 + 255) / 256, 256>>>(img1, img2, 8, 32);

    // init block (slot 0, nc_in=1, full-res only) with fused border
    smmain_kernel<<<dim3(20, 8, 8), 128>>>(image, img1, img2,
        x_in, x_in, x_in, x0a, x0a, x0a, tabDup, tabBDup, tabW5, tabB, 1, 0, 0);

    // downsample x
    down_kernel<<<(64 * 64 * 64 + 255) / 256, 256>>>(x0a, x1a, 64, 64);
    down_kernel<<<(64 * 32 * 32 + 255) / 256, 256>>>(x1a, x2a, 64, 32);

    float *xc = x0a, *xn = x0b;
    float *x1c = x1a, *x1n = x1b;
    float *x2c = x2a, *x2n = x2b;

    for (int t = 0; t < 4; t++) {
        smmain_kernel<<<dim3(28, 8, 8), 128>>>(image, img1, img2,
            xc, x1c, x2c, xn, x1n, x2n, tabDup, tabBDup, tabW5, tabB,
            8, 1 + 3 * t, 1);
        { float* tp = xc;  xc = xn;   xn = tp; }
        { float* tp = x1c; x1c = x1n; x1n = tp; }
        { float* tp = x2c; x2c = x2n; x2n = tp; }
    }

    combine_kernel<<<(8 * 128 * 128 + 255) / 256, 256>>>(
        xc, x1c, x2c, w5, b5, w6, b6, (float*)d_out);
}

// round 15
// speedup vs baseline: 1.5481x; 1.0438x over previous
#include <cuda_runtime.h>
#include <math.h>

// ---------------------------------------------------------------------------
// SMModel — composed-5x5, packed f32x2. Exact 771us (R5) configuration:
// 128 thr/block, 2x4 px/thread, kg-split acc, CHG=4, simg staging stage,
// fused border blocks. Single delta: xq apply-loads moved AFTER the conv
// loop (shorter live range; consumed only in the apply step).
// ---------------------------------------------------------------------------

#define NC    8
#define HID   20
#define CHG   4

typedef unsigned long long ull;

__device__ __align__(16) float g_buf[5064832];

__device__ __forceinline__ float elu_f(float v) {
    return v > 0.f ? v : (expf(v) - 1.f);
}
__device__ __forceinline__ ull pk(float lo, float hi) {
    ull r; asm("mov.b64 %0, {%1, %2};" : "=l"(r) : "f"(lo), "f"(hi)); return r;
}
__device__ __forceinline__ void upk(ull v, float& lo, float& hi) {
    asm("mov.b64 {%0, %1}, %2;" : "=f"(lo), "=f"(hi) : "l"(v));
}
__device__ __forceinline__ ull fma2(ull a, ull b, ull c) {
    ull d; asm("fma.rn.f32x2 %0, %1, %2, %3;" : "=l"(d) : "l"(a), "l"(b), "l"(c)); return d;
}

// ---------------------------------------------------------------------------
// compose: ALL 13 layers, one launch.
// tabW5[l][cls9][64][9][25] f, tabB[l][cls9][64][9] f,
// tabDup[l][64][25*12] ull (cls0 pairs, slot d*12+kg*4+j), tabBDup[l][64][12].
// ---------------------------------------------------------------------------
__global__ void compose_kernel(
    const float* __restrict__ iW1, const float* __restrict__ ib1,
    const float* __restrict__ iW2, const float* __restrict__ ib2,
    const float* __restrict__ bW1, const float* __restrict__ bb1,
    const float* __restrict__ bW2, const float* __restrict__ bb2,
    float* __restrict__ tabW5, float* __restrict__ tabB,
    ull* __restrict__ tabDup, ull* __restrict__ tabBDup)
{
    int idx = blockIdx.x * blockDim.x + threadIdx.x;
    if (idx >= 13 * 5184) return;
    int l = idx / 5184;
    int r0 = idx % 5184;
    int cls = r0 / 576;
    int g = (r0 % 576) / 9, k = r0 % 9;
    if (l == 0 && g >= 8) return;

    const float *W1, *b1, *W2, *b2;
    if (l == 0) { W1 = iW1; b1 = ib1; W2 = iW2; b2 = ib2; }
    else {
        int m = l - 1;
        W1 = bW1 + (size_t)m * 1280 * 9;  b1 = bb1 + (size_t)m * 1280;
        W2 = bW2 + (size_t)m * 576 * 180; b2 = bb2 + (size_t)m * 576;
    }

    float T[25];
#pragma unroll
    for (int j = 0; j < 25; j++) T[j] = 0.f;
    float bias = b2[g * 9 + k];

    for (int q = 0; q < 9; q++) {
        int qy = q / 3 - 1, qx = q % 3 - 1;
        bool vyl = (qy >= 0), vyh = (qy <= 0), vxl = (qx >= 0), vxh = (qx <= 0);
        bool in;
        switch (cls) {
            case 0: in = true; break;
            case 1: in = vyl; break;
            case 2: in = vyh; break;
            case 3: in = vxl; break;
            case 4: in = vxh; break;
            case 5: in = vyl && vxl; break;
            case 6: in = vyl && vxh; break;
            case 7: in = vyh && vxl; break;
            default: in = vyh && vxh; break;
        }
        if (!in) continue;
        for (int c = 0; c < HID; c++) {
            float w2 = W2[((size_t)(g * 9 + k) * HID + c) * 9 + q];
            bias += b1[g * HID + c] * w2;
#pragma unroll
            for (int r = 0; r < 9; r++) {
                int ry = r / 3 - 1, rx = r % 3 - 1;
                T[(qy + ry + 2) * 5 + (qx + rx + 2)] += w2 * W1[(size_t)(g * HID + c) * 9 + r];
            }
        }
    }

    float* To = tabW5 + (size_t)l * 129600 + ((size_t)(cls * 64 + g) * 9 + k) * 25;
#pragma unroll
    for (int j = 0; j < 25; j++) To[j] = T[j];
    tabB[(size_t)l * 5184 + (size_t)(cls * 64 + g) * 9 + k] = bias;

    if (cls == 0) {
        ull* dd = tabDup + (size_t)l * 19200 + (size_t)g * 300;
        int kg = k / 3, j = k % 3;
#pragma unroll
        for (int d = 0; d < 25; d++) dd[d * 12 + kg * 4 + j] = pk(T[d], T[d]);
        tabBDup[(size_t)l * 768 + g * 12 + kg * 4 + j] = pk(bias, bias);
    }
}

// ---------------------------------------------------------------------------
__device__ __forceinline__ void load_row(const ull* __restrict__ spair,
                                         int row, int pqx, ull (&R)[7])
{
    const ull* base = spair + row * 36 + pqx;
    ulonglong2 t0 = *reinterpret_cast<const ulonglong2*>(base);
    ulonglong2 t1 = *reinterpret_cast<const ulonglong2*>(base + 2);
    ulonglong2 t2 = *reinterpret_cast<const ulonglong2*>(base + 4);
    R[0] = t0.x; R[1] = t0.y; R[2] = t1.x; R[3] = t1.y;
    R[4] = t2.x; R[5] = t2.y; R[6] = base[6];
}

// one dy row-step: 5 dx x 3 j x 4 acc (inline weight loads, as in 771us)
__device__ __forceinline__ void conv_step(const ull* __restrict__ wrow,
                                          const ull (&R)[7], const ull (&S)[7],
                                          ull (&acc)[3][2][2])
{
#pragma unroll
    for (int dx = 0; dx < 5; dx++) {
        const ull* wp = wrow + dx * 12;
        ulonglong2 t = *reinterpret_cast<const ulonglong2*>(wp);
        ull w0 = t.x, w1 = t.y, w2 = wp[2];
        acc[0][0][0] = fma2(R[dx],     w0, acc[0][0][0]);
        acc[0][0][1] = fma2(R[dx + 2], w0, acc[0][0][1]);
        acc[0][1][0] = fma2(S[dx],     w0, acc[0][1][0]);
        acc[0][1][1] = fma2(S[dx + 2], w0, acc[0][1][1]);
        acc[1][0][0] = fma2(R[dx],     w1, acc[1][0][0]);
        acc[1][0][1] = fma2(R[dx + 2], w1, acc[1][0][1]);
        acc[1][1][0] = fma2(S[dx],     w1, acc[1][1][0]);
        acc[1][1][1] = fma2(S[dx + 2], w1, acc[1][1][1]);
        acc[2][0][0] = fma2(R[dx],     w2, acc[2][0][0]);
        acc[2][0][1] = fma2(R[dx + 2], w2, acc[2][0][1]);
        acc[2][1][0] = fma2(S[dx],     w2, acc[2][1][0]);
        acc[2][1][1] = fma2(S[dx + 2], w2, acc[2][1][1]);
    }
}

// ---------------------------------------------------------------------------
// main + border fused. 128 threads/block, thread = 2 rows x 4 cols.
// ---------------------------------------------------------------------------
__global__ __launch_bounds__(128) void smmain_kernel(
    const float* __restrict__ img0, const float* __restrict__ img1p, const float* __restrict__ img2p,
    const float* __restrict__ xin0, const float* __restrict__ xin1, const float* __restrict__ xin2,
    float* __restrict__ out0, float* __restrict__ out1, float* __restrict__ out2,
    const ull* __restrict__ tabDup, const ull* __restrict__ tabBDup,
    const float* __restrict__ tabW5, const float* __restrict__ tabB,
    int nc_in, int slotBase, int mode)
{
    const int bx = blockIdx.x;
    const int o = blockIdx.y, b = blockIdx.z;
    const int tid = threadIdx.x;
    const int mainX = (mode == 0) ? 16 : 21;

    if (bx >= mainX) {
        // ---------------- border path ----------------
        int bp = (bx - mainX) * 128 + tid;
        int limit = (mode == 0) ? 508 : 884;
        if (bp >= limit) return;
        int s, e;
        if (bp < 508)      { s = 0; e = bp; }
        else if (bp < 760) { s = 1; e = bp - 508; }
        else               { s = 2; e = bp - 760; }
        const float* img = (s == 0) ? img0 : (s == 1) ? img1p : img2p;
        const float* xin = (s == 0) ? xin0 : (s == 1) ? xin1 : xin2;
        float* out = (s == 0) ? out0 : (s == 1) ? out1 : out2;
        const int N = 128 >> s;
        const int slot = slotBase + s;

        int py, px;
        if (e < N)              { py = 0;     px = e; }
        else if (e < 2 * N)     { py = N - 1; px = e - N; }
        else if (e < 3 * N - 2) { py = e - 2 * N + 1;       px = 0; }
        else                    { py = e - (3 * N - 2) + 1; px = N - 1; }

        bool Tt = (py == 0), Bb = (py == N - 1), Ll = (px == 0), Rr = (px == N - 1);
        int cls = Tt ? (Ll ? 5 : (Rr ? 6 : 1))
                     : (Bb ? (Ll ? 7 : (Rr ? 8 : 2)) : (Ll ? 3 : 4));

        float w[25];
        const float* ibp = img + (size_t)b * N * N;
#pragma unroll
        for (int dy = 0; dy < 5; dy++)
#pragma unroll
            for (int dx = 0; dx < 5; dx++) {
                int iy = py - 2 + dy, ix = px - 2 + dx;
                w[dy * 5 + dx] = (iy >= 0 && iy < N && ix >= 0 && ix < N) ? ibp[iy * N + ix] : 0.f;
            }

        float accv = 0.f;
        for (int i = 0; i < nc_in; i++) {
            int g = o * nc_in + i;
            const float* tb = tabW5 + (size_t)slot * 129600 + ((size_t)(cls * 64 + g) * 9) * 25;
            const float* bb = tabB + (size_t)slot * 5184 + (size_t)(cls * 64 + g) * 9;
            const float* xb = xin + ((size_t)b * nc_in + i) * N * N;
            float Kf[9];
#pragma unroll
            for (int k = 0; k < 9; k++) Kf[k] = bb[k];
#pragma unroll
            for (int j = 0; j < 25; j++) {
                float v = w[j];
#pragma unroll
                for (int k = 0; k < 9; k++) Kf[k] += tb[k * 25 + j] * v;
            }
#pragma unroll
            for (int k = 0; k < 9; k++) {
                int yy = py + k / 3 - 1, xx = px + k % 3 - 1;
                float xv = (yy >= 0 && yy < N && xx >= 0 && xx < N) ? xb[yy * N + xx] : 0.f;
                accv += Kf[k] * xv;
            }
        }
        out[((size_t)b * NC + o) * N * N + py * N + px] = elu_f(accv);
        return;
    }

    // ---------------- main (interior) path ----------------
    __shared__ __align__(16) float simg[36 * 36];          // 5184 B
    __shared__ __align__(16) ull   spair[36 * 36];         // 10368 B
    __shared__ __align__(16) float sxs[CHG * 34 * 36];     // 19584 B
    __shared__ __align__(16) ull   sWd[CHG * 300];         // 9600 B
    __shared__ __align__(16) ull   sBd[CHG * 12];          // 384 B

    int s, tile;
    const float *img, *xin;
    float* out;
    if (bx < 16)      { s = 0; tile = bx;      img = img0;  xin = xin0; out = out0; }
    else if (bx < 20) { s = 1; tile = bx - 16; img = img1p; xin = xin1; out = out1; }
    else              { s = 2; tile = bx - 20; img = img2p; xin = xin2; out = out2; }
    const int N = 128 >> s;
    const int tilesX = N / 32;
    const int tx0 = (tile % tilesX) * 32, ty0 = (tile / tilesX) * 32;
    const int slot = slotBase + s;
    const int pqx = (tid & 7) * 4;
    const int pqy = (tid >> 3) * 2;

    // image tile, halo 2, zero-padded (simg stage — load-bearing for regs=128)
    const float* ib = img + (size_t)b * N * N;
    for (int idx = tid; idx < 36 * 36; idx += 128) {
        int ly = idx / 36, lx = idx % 36;
        int gy = ty0 - 2 + ly, gx = tx0 - 2 + lx;
        simg[idx] = (gy >= 0 && gy < N && gx >= 0 && gx < N) ? ib[gy * N + gx] : 0.f;
    }
    __syncthreads();
    for (int idx = tid; idx < 36 * 35; idx += 128) {
        int ly = idx / 35, lx = idx % 35;
        spair[ly * 36 + lx] = pk(simg[ly * 36 + lx], simg[ly * 36 + lx + 1]);
    }
    // (sync before compute provided by the per-phase post-load barrier)

    ull oacc[2][2];
    oacc[0][0] = 0ull; oacc[0][1] = 0ull; oacc[1][0] = 0ull; oacc[1][1] = 0ull;

    for (int i0 = 0; i0 < nc_in; i0 += CHG) {
        const int chg = (nc_in - i0 < CHG) ? (nc_in - i0) : CHG;
        __syncthreads();   // previous phase compute done (and spair build, phase 0)

        // stage chg channels: x tiles, weights, biases
        for (int idx = tid; idx < chg * 1156; idx += 128) {
            int ci = idx / 1156, r = idx % 1156;
            int ly = r / 34, lx = r % 34;
            int gy = ty0 - 1 + ly, gx = tx0 - 1 + lx;
            const float* xb = xin + ((size_t)b * nc_in + (i0 + ci)) * N * N;
            sxs[ci * 1224 + ly * 36 + lx] =
                (gy >= 0 && gy < N && gx >= 0 && gx < N) ? xb[gy * N + gx] : 0.f;
        }
        for (int idx = tid; idx < chg * 300; idx += 128) {
            int ci = idx / 300, j = idx % 300;
            int g = o * nc_in + i0 + ci;
            sWd[ci * 300 + j] = tabDup[(size_t)slot * 19200 + (size_t)g * 300 + j];
        }
        if (tid < chg * 12) {
            int ci = tid / 12, j = tid % 12;
            int g = o * nc_in + i0 + ci;
            sBd[ci * 12 + j] = tabBDup[(size_t)slot * 768 + (size_t)g * 12 + j];
        }
        __syncthreads();

#pragma unroll 1
        for (int ci = 0; ci < chg; ci++) {
            const ull*   wd = sWd + ci * 300;
            const ull*   bd = sBd + ci * 12;
            const float* xc = sxs + ci * 1224;

#pragma unroll 1
            for (int kg = 0; kg < 3; kg++) {
                ull acc[3][2][2];
#pragma unroll
                for (int j = 0; j < 3; j++) {
                    ull bb = bd[kg * 4 + j];
                    acc[j][0][0] = bb; acc[j][0][1] = bb;
                    acc[j][1][0] = bb; acc[j][1][1] = bb;
                }

                const ull* wk = wd + kg * 4;
                ull A[7], B[7];
                load_row(spair, pqy,     pqx, A);
                load_row(spair, pqy + 1, pqx, B);
                conv_step(wk,          A, B, acc);
                load_row(spair, pqy + 2, pqx, A);
                conv_step(wk + 60,     B, A, acc);
                load_row(spair, pqy + 3, pqx, B);
                conv_step(wk + 120,    A, B, acc);
                load_row(spair, pqy + 4, pqx, A);
                conv_step(wk + 180,    B, A, acc);
                load_row(spair, pqy + 5, pqx, B);
                conv_step(wk + 240,    A, B, acc);

                // apply: load x pairs ONLY NOW (short live range — the one delta)
#pragma unroll
                for (int rr = 0; rr < 2; rr++) {
                    const float* xr = xc + (pqy + kg + rr) * 36 + pqx;
                    float4 q4 = *reinterpret_cast<const float4*>(xr);
                    float2 q2 = *reinterpret_cast<const float2*>(xr + 4);
                    ull x0 = pk(q4.x, q4.y), x1 = pk(q4.y, q4.z), x2 = pk(q4.z, q4.w);
                    ull x3 = pk(q4.w, q2.x), x4 = pk(q2.x, q2.y);
                    oacc[rr][0] = fma2(acc[0][rr][0], x0, oacc[rr][0]);
                    oacc[rr][1] = fma2(acc[0][rr][1], x2, oacc[rr][1]);
                    oacc[rr][0] = fma2(acc[1][rr][0], x1, oacc[rr][0]);
                    oacc[rr][1] = fma2(acc[1][rr][1], x3, oacc[rr][1]);
                    oacc[rr][0] = fma2(acc[2][rr][0], x2, oacc[rr][0]);
                    oacc[rr][1] = fma2(acc[2][rr][1], x4, oacc[rr][1]);
                }
            }
        }
    }

    float* ob = out + ((size_t)b * NC + o) * N * N;
#pragma unroll
    for (int sy = 0; sy < 2; sy++) {
#pragma unroll
        for (int cp = 0; cp < 2; cp++) {
            float lo, hi;
            upk(oacc[sy][cp], lo, hi);
            int row = ty0 + pqy + sy, col = tx0 + pqx + 2 * cp;
            if (row > 0 && row < N - 1) {
                if (col > 0 && col < N - 1)         ob[row * N + col]     = elu_f(lo);
                if (col + 1 > 0 && col + 1 < N - 1) ob[row * N + col + 1] = elu_f(hi);
            }
        }
    }
}

// ---------------------------------------------------------------------------
__global__ void down_kernel(const float* __restrict__ in, float* __restrict__ out,
                            int C, int No)
{
    int idx = blockIdx.x * blockDim.x + threadIdx.x;
    int total = C * No * No;
    if (idx >= total) return;
    int c = idx / (No * No);
    int p = idx % (No * No);
    int h = p / No, w = p % No;
    int Ni = No * 2;
    const float* ib = in + (size_t)c * Ni * Ni;
    float sv = ib[(2 * h) * Ni + 2 * w] + ib[(2 * h) * Ni + 2 * w + 1]
             + ib[(2 * h + 1) * Ni + 2 * w] + ib[(2 * h + 1) * Ni + 2 * w + 1];
    out[idx] = 0.25f * sv;
}

__global__ void combine_kernel(const float* __restrict__ x0,
                               const float* __restrict__ x1,
                               const float* __restrict__ x2,
                               const float* __restrict__ w5, const float* __restrict__ b5,
                               const float* __restrict__ w6, const float* __restrict__ b6,
                               float* __restrict__ out)
{
    int idx = blockIdx.x * blockDim.x + threadIdx.x;
    if (idx >= 8 * 128 * 128) return;
    int b = idx / (128 * 128);
    int p = idx % (128 * 128);
    int h = p / 128, w = p % 128;
    float v[NC];
#pragma unroll
    for (int c = 0; c < NC; c++) {
        v[c] = x0[((size_t)b * NC + c) * 16384 + p]
             + x1[((size_t)b * NC + c) * 4096 + (h >> 1) * 64 + (w >> 1)]
             + x2[((size_t)b * NC + c) * 1024 + (h >> 2) * 32 + (w >> 2)];
    }
    float accv = b6[0];
#pragma unroll
    for (int o = 0; o < NC; o++) {
        float y = b5[o];
#pragma unroll
        for (int c = 0; c < NC; c++) y += w5[o * NC + c] * v[c];
        y = elu_f(y);
        accv += w6[o] * y;
    }
    out[idx] = accv;
}

// ---------------------------------------------------------------------------
extern "C" void kernel_launch(void* const* d_in, const int* in_sizes, int n_in,
                              void* d_out, int out_size)
{
    const float* image = (const float*)d_in[0];
    const float* x_in  = (const float*)d_in[1];
    const float* iW1   = (const float*)d_in[2];
    const float* ib1   = (const float*)d_in[3];
    const float* iW2   = (const float*)d_in[4];
    const float* ib2   = (const float*)d_in[5];
    const float* bW1   = (const float*)d_in[6];
    const float* bb1   = (const float*)d_in[7];
    const float* bW2   = (const float*)d_in[8];
    const float* bb2   = (const float*)d_in[9];
    const float* w5    = (const float*)d_in[10];
    const float* b5    = (const float*)d_in[11];
    const float* w6    = (const float*)d_in[12];
    const float* b6    = (const float*)d_in[13];

    float* base;
    cudaGetSymbolAddress((void**)&base, g_buf);
    float* img1 = base;
    float* img2 = img1 + 32768;
    float* x0a  = img2 + 8192;
    float* x0b  = x0a + 1048576;
    float* x1a  = x0b + 1048576;
    float* x1b  = x1a + 262144;
    float* x2a  = x1b + 262144;
    float* x2b  = x2a + 65536;
    float* tabW5 = x2b + 65536;                // 13*129600
    float* tabB  = tabW5 + 13 * 129600;        // 13*5184
    ull*   tabDup  = (ull*)(tabB + 13 * 5184); // 13*19200 ull
    ull*   tabBDup = tabDup + 13 * 19200;      // 13*768 ull

    // all tables upfront (x-independent)
    compose_kernel<<<(13 * 5184 + 127) / 128, 128>>>(
        iW1, ib1, iW2, ib2, bW1, bb1, bW2, bb2, tabW5, tabB, tabDup, tabBDup);

    // image pyramid
    down_kernel<<<(8 * 64 * 64 + 255) / 256, 256>>>(image, img1, 8, 64);
    down_kernel<<<(8 * 32 * 32 + 255) / 256, 256>>>(img1, img2, 8, 32);

    // init block (slot 0, nc_in=1, full-res only) with fused border
    smmain_kernel<<<dim3(20, 8, 8), 128>>>(image, img1, img2,
        x_in, x_in, x_in, x0a, x0a, x0a, tabDup, tabBDup, tabW5, tabB, 1, 0, 0);

    // downsample x
    down_kernel<<<(64 * 64 * 64 + 255) / 256, 256>>>(x0a, x1a, 64, 64);
    down_kernel<<<(64 * 32 * 32 + 255) / 256, 256>>>(x1a, x2a, 64, 32);

    float *xc = x0a, *xn = x0b;
    float *x1c = x1a, *x1n = x1b;
    float *x2c = x2a, *x2n = x2b;

    for (int t = 0; t < 4; t++) {
        smmain_kernel<<<dim3(28, 8, 8), 128>>>(image, img1, img2,
            xc, x1c, x2c, xn, x1n, x2n, tabDup, tabBDup, tabW5, tabB,
            8, 1 + 3 * t, 1);
        { float* tp = xc;  xc = xn;   xn = tp; }
        { float* tp = x1c; x1c = x1n; x1n = tp; }
        { float* tp = x2c; x2c = x2n; x2n = tp; }
    }

    combine_kernel<<<(8 * 128 * 128 + 255) / 256, 256>>>(
        xc, x1c, x2c, w5, b5, w6, b6, (float*)d_out);
}

// round 16
// speedup vs baseline: 1.6001x; 1.0336x over previous
#include <cuda_runtime.h>
#include <math.h>

// ---------------------------------------------------------------------------
// SMModel — composed-5x5, packed f32x2, channel-group phasing, vector LDS.
// Hot kernel byte-identical to the measured 771us optimum (R5 config).
// Only delta: down-sample launches fused (level-2 = 4x4 mean of level-0),
// launch count 11 -> 9. Nothing in smmain/compose changed.
// ---------------------------------------------------------------------------

#define NC    8
#define HID   20
#define CHG   4

typedef unsigned long long ull;

__device__ __align__(16) float g_buf[5064832];

__device__ __forceinline__ float elu_f(float v) {
    return v > 0.f ? v : (expf(v) - 1.f);
}
__device__ __forceinline__ ull pk(float lo, float hi) {
    ull r; asm("mov.b64 %0, {%1, %2};" : "=l"(r) : "f"(lo), "f"(hi)); return r;
}
__device__ __forceinline__ void upk(ull v, float& lo, float& hi) {
    asm("mov.b64 {%0, %1}, %2;" : "=f"(lo), "=f"(hi) : "l"(v));
}
__device__ __forceinline__ ull fma2(ull a, ull b, ull c) {
    ull d; asm("fma.rn.f32x2 %0, %1, %2, %3;" : "=l"(d) : "l"(a), "l"(b), "l"(c)); return d;
}

// ---------------------------------------------------------------------------
// compose: ALL 13 layers, one launch.
// tabW5[l][cls9][64][9][25] f, tabB[l][cls9][64][9] f,
// tabDup[l][64][25*12] ull (cls0 pairs, slot d*12+kg*4+j), tabBDup[l][64][12].
// ---------------------------------------------------------------------------
__global__ void compose_kernel(
    const float* __restrict__ iW1, const float* __restrict__ ib1,
    const float* __restrict__ iW2, const float* __restrict__ ib2,
    const float* __restrict__ bW1, const float* __restrict__ bb1,
    const float* __restrict__ bW2, const float* __restrict__ bb2,
    float* __restrict__ tabW5, float* __restrict__ tabB,
    ull* __restrict__ tabDup, ull* __restrict__ tabBDup)
{
    int idx = blockIdx.x * blockDim.x + threadIdx.x;
    if (idx >= 13 * 5184) return;
    int l = idx / 5184;
    int r0 = idx % 5184;
    int cls = r0 / 576;
    int g = (r0 % 576) / 9, k = r0 % 9;
    if (l == 0 && g >= 8) return;

    const float *W1, *b1, *W2, *b2;
    if (l == 0) { W1 = iW1; b1 = ib1; W2 = iW2; b2 = ib2; }
    else {
        int m = l - 1;
        W1 = bW1 + (size_t)m * 1280 * 9;  b1 = bb1 + (size_t)m * 1280;
        W2 = bW2 + (size_t)m * 576 * 180; b2 = bb2 + (size_t)m * 576;
    }

    float T[25];
#pragma unroll
    for (int j = 0; j < 25; j++) T[j] = 0.f;
    float bias = b2[g * 9 + k];

    for (int q = 0; q < 9; q++) {
        int qy = q / 3 - 1, qx = q % 3 - 1;
        bool vyl = (qy >= 0), vyh = (qy <= 0), vxl = (qx >= 0), vxh = (qx <= 0);
        bool in;
        switch (cls) {
            case 0: in = true; break;
            case 1: in = vyl; break;
            case 2: in = vyh; break;
            case 3: in = vxl; break;
            case 4: in = vxh; break;
            case 5: in = vyl && vxl; break;
            case 6: in = vyl && vxh; break;
            case 7: in = vyh && vxl; break;
            default: in = vyh && vxh; break;
        }
        if (!in) continue;
        for (int c = 0; c < HID; c++) {
            float w2 = W2[((size_t)(g * 9 + k) * HID + c) * 9 + q];
            bias += b1[g * HID + c] * w2;
#pragma unroll
            for (int r = 0; r < 9; r++) {
                int ry = r / 3 - 1, rx = r % 3 - 1;
                T[(qy + ry + 2) * 5 + (qx + rx + 2)] += w2 * W1[(size_t)(g * HID + c) * 9 + r];
            }
        }
    }

    float* To = tabW5 + (size_t)l * 129600 + ((size_t)(cls * 64 + g) * 9 + k) * 25;
#pragma unroll
    for (int j = 0; j < 25; j++) To[j] = T[j];
    tabB[(size_t)l * 5184 + (size_t)(cls * 64 + g) * 9 + k] = bias;

    if (cls == 0) {
        ull* dd = tabDup + (size_t)l * 19200 + (size_t)g * 300;
        int kg = k / 3, j = k % 3;
#pragma unroll
        for (int d = 0; d < 25; d++) dd[d * 12 + kg * 4 + j] = pk(T[d], T[d]);
        tabBDup[(size_t)l * 768 + g * 12 + kg * 4 + j] = pk(bias, bias);
    }
}

// ---------------------------------------------------------------------------
__device__ __forceinline__ void load_row(const ull* __restrict__ spair,
                                         int row, int pqx, ull (&R)[7])
{
    const ull* base = spair + row * 36 + pqx;
    ulonglong2 t0 = *reinterpret_cast<const ulonglong2*>(base);
    ulonglong2 t1 = *reinterpret_cast<const ulonglong2*>(base + 2);
    ulonglong2 t2 = *reinterpret_cast<const ulonglong2*>(base + 4);
    R[0] = t0.x; R[1] = t0.y; R[2] = t1.x; R[3] = t1.y;
    R[4] = t2.x; R[5] = t2.y; R[6] = base[6];
}

// one dy step: 5 dx x 3 j x (2 rows x 2 colpairs)
__device__ __forceinline__ void conv_step(const ull* __restrict__ wrow,
                                          const ull (&R)[7], const ull (&S)[7],
                                          ull (&acc)[3][2][2])
{
#pragma unroll
    for (int dx = 0; dx < 5; dx++) {
        const ull* wp = wrow + dx * 12;
        ulonglong2 t = *reinterpret_cast<const ulonglong2*>(wp);
        ull w0 = t.x, w1 = t.y, w2 = wp[2];
        acc[0][0][0] = fma2(R[dx],     w0, acc[0][0][0]);
        acc[0][0][1] = fma2(R[dx + 2], w0, acc[0][0][1]);
        acc[0][1][0] = fma2(S[dx],     w0, acc[0][1][0]);
        acc[0][1][1] = fma2(S[dx + 2], w0, acc[0][1][1]);
        acc[1][0][0] = fma2(R[dx],     w1, acc[1][0][0]);
        acc[1][0][1] = fma2(R[dx + 2], w1, acc[1][0][1]);
        acc[1][1][0] = fma2(S[dx],     w1, acc[1][1][0]);
        acc[1][1][1] = fma2(S[dx + 2], w1, acc[1][1][1]);
        acc[2][0][0] = fma2(R[dx],     w2, acc[2][0][0]);
        acc[2][0][1] = fma2(R[dx + 2], w2, acc[2][0][1]);
        acc[2][1][0] = fma2(S[dx],     w2, acc[2][1][0]);
        acc[2][1][1] = fma2(S[dx + 2], w2, acc[2][1][1]);
    }
}

// ---------------------------------------------------------------------------
// main + border fused; dynamic smem 45120 bytes. (byte-identical to 771us)
// ---------------------------------------------------------------------------
__global__ __launch_bounds__(128) void smmain_kernel(
    const float* __restrict__ img0, const float* __restrict__ img1p, const float* __restrict__ img2p,
    const float* __restrict__ xin0, const float* __restrict__ xin1, const float* __restrict__ xin2,
    float* __restrict__ out0, float* __restrict__ out1, float* __restrict__ out2,
    const ull* __restrict__ tabDup, const ull* __restrict__ tabBDup,
    const float* __restrict__ tabW5, const float* __restrict__ tabB,
    int nc_in, int slotBase, int mode)
{
    const int bx = blockIdx.x;
    const int o = blockIdx.y, b = blockIdx.z;
    const int tid = threadIdx.x;
    const int mainX = (mode == 0) ? 16 : 21;

    if (bx >= mainX) {
        // ---------------- border path ----------------
        int bp = (bx - mainX) * 128 + tid;
        int limit = (mode == 0) ? 508 : 884;
        if (bp >= limit) return;
        int s, e;
        if (bp < 508)      { s = 0; e = bp; }
        else if (bp < 760) { s = 1; e = bp - 508; }
        else               { s = 2; e = bp - 760; }
        const float* img = (s == 0) ? img0 : (s == 1) ? img1p : img2p;
        const float* xin = (s == 0) ? xin0 : (s == 1) ? xin1 : xin2;
        float* out = (s == 0) ? out0 : (s == 1) ? out1 : out2;
        const int N = 128 >> s;
        const int slot = slotBase + s;

        int py, px;
        if (e < N)              { py = 0;     px = e; }
        else if (e < 2 * N)     { py = N - 1; px = e - N; }
        else if (e < 3 * N - 2) { py = e - 2 * N + 1;       px = 0; }
        else                    { py = e - (3 * N - 2) + 1; px = N - 1; }

        bool Tt = (py == 0), Bb = (py == N - 1), Ll = (px == 0), Rr = (px == N - 1);
        int cls = Tt ? (Ll ? 5 : (Rr ? 6 : 1))
                     : (Bb ? (Ll ? 7 : (Rr ? 8 : 2)) : (Ll ? 3 : 4));

        float w[25];
        const float* ibp = img + (size_t)b * N * N;
#pragma unroll
        for (int dy = 0; dy < 5; dy++)
#pragma unroll
            for (int dx = 0; dx < 5; dx++) {
                int iy = py - 2 + dy, ix = px - 2 + dx;
                w[dy * 5 + dx] = (iy >= 0 && iy < N && ix >= 0 && ix < N) ? ibp[iy * N + ix] : 0.f;
            }

        float accv = 0.f;
        for (int i = 0; i < nc_in; i++) {
            int g = o * nc_in + i;
            const float* tb = tabW5 + (size_t)slot * 129600 + ((size_t)(cls * 64 + g) * 9) * 25;
            const float* bb = tabB + (size_t)slot * 5184 + (size_t)(cls * 64 + g) * 9;
            const float* xb = xin + ((size_t)b * nc_in + i) * N * N;
            float Kf[9];
#pragma unroll
            for (int k = 0; k < 9; k++) Kf[k] = bb[k];
#pragma unroll
            for (int j = 0; j < 25; j++) {
                float v = w[j];
#pragma unroll
                for (int k = 0; k < 9; k++) Kf[k] += tb[k * 25 + j] * v;
            }
#pragma unroll
            for (int k = 0; k < 9; k++) {
                int yy = py + k / 3 - 1, xx = px + k % 3 - 1;
                float xv = (yy >= 0 && yy < N && xx >= 0 && xx < N) ? xb[yy * N + xx] : 0.f;
                accv += Kf[k] * xv;
            }
        }
        out[((size_t)b * NC + o) * N * N + py * N + px] = elu_f(accv);
        return;
    }

    // ---------------- main (interior) path ----------------
    extern __shared__ __align__(16) char smraw[];
    float* simg  = (float*)smraw;                 // 36*36 f        = 5184 B
    ull*   spair = (ull*)(smraw + 5184);          // 36*36 ull      = 10368 B
    float* sxs   = (float*)(smraw + 15552);       // 4 * 34*36 f    = 19584 B
    ull*   sWd   = (ull*)(smraw + 35136);         // 4 * 300 ull    = 9600 B
    ull*   sBd   = (ull*)(smraw + 44736);         // 4 * 12 ull     = 384 B

    int s, tile;
    const float *img, *xin;
    float* out;
    if (bx < 16)      { s = 0; tile = bx;      img = img0;  xin = xin0; out = out0; }
    else if (bx < 20) { s = 1; tile = bx - 16; img = img1p; xin = xin1; out = out1; }
    else              { s = 2; tile = bx - 20; img = img2p; xin = xin2; out = out2; }
    const int N = 128 >> s;
    const int tilesX = N / 32;
    const int tx0 = (tile % tilesX) * 32, ty0 = (tile / tilesX) * 32;
    const int slot = slotBase + s;
    const int pqx = (tid & 7) * 4;
    const int pqy = (tid >> 3) * 2;

    const float* ib = img + (size_t)b * N * N;
    for (int idx = tid; idx < 36 * 36; idx += 128) {
        int ly = idx / 36, lx = idx % 36;
        int gy = ty0 - 2 + ly, gx = tx0 - 2 + lx;
        simg[idx] = (gy >= 0 && gy < N && gx >= 0 && gx < N) ? ib[gy * N + gx] : 0.f;
    }
    __syncthreads();
    for (int idx = tid; idx < 36 * 35; idx += 128) {
        int ly = idx / 35, lx = idx % 35;
        spair[ly * 36 + lx] = pk(simg[ly * 36 + lx], simg[ly * 36 + lx + 1]);
    }
    // (sync before compute provided by the per-phase post-load barrier)

    ull oacc[2][2];
    oacc[0][0] = 0ull; oacc[0][1] = 0ull; oacc[1][0] = 0ull; oacc[1][1] = 0ull;

    for (int i0 = 0; i0 < nc_in; i0 += CHG) {
        const int chg = (nc_in - i0 < CHG) ? (nc_in - i0) : CHG;
        __syncthreads();   // previous phase compute done

        // stage chg channels: x tiles, weights, biases
        for (int idx = tid; idx < chg * 1156; idx += 128) {
            int ci = idx / 1156, r = idx % 1156;
            int ly = r / 34, lx = r % 34;
            int gy = ty0 - 1 + ly, gx = tx0 - 1 + lx;
            const float* xb = xin + ((size_t)b * nc_in + (i0 + ci)) * N * N;
            sxs[ci * 1224 + ly * 36 + lx] =
                (gy >= 0 && gy < N && gx >= 0 && gx < N) ? xb[gy * N + gx] : 0.f;
        }
        for (int idx = tid; idx < chg * 300; idx += 128) {
            int ci = idx / 300, j = idx % 300;
            int g = o * nc_in + i0 + ci;
            sWd[ci * 300 + j] = tabDup[(size_t)slot * 19200 + (size_t)g * 300 + j];
        }
        if (tid < chg * 12) {
            int ci = tid / 12, j = tid % 12;
            int g = o * nc_in + i0 + ci;
            sBd[ci * 12 + j] = tabBDup[(size_t)slot * 768 + (size_t)g * 12 + j];
        }
        __syncthreads();

#pragma unroll 1
        for (int ci = 0; ci < chg; ci++) {
            const ull*   wd = sWd + ci * 300;
            const ull*   bd = sBd + ci * 12;
            const float* xc = sxs + ci * 1224;

#pragma unroll 1
            for (int kg = 0; kg < 3; kg++) {
                // x pairs for rows pqy+kg, pqy+kg+1
                ull xq[2][5];
#pragma unroll
                for (int rr = 0; rr < 2; rr++) {
                    const float* xr = xc + (pqy + kg + rr) * 36 + pqx;
                    float4 q4 = *reinterpret_cast<const float4*>(xr);
                    float2 q2 = *reinterpret_cast<const float2*>(xr + 4);
                    xq[rr][0] = pk(q4.x, q4.y); xq[rr][1] = pk(q4.y, q4.z);
                    xq[rr][2] = pk(q4.z, q4.w); xq[rr][3] = pk(q4.w, q2.x);
                    xq[rr][4] = pk(q2.x, q2.y);
                }

                ull acc[3][2][2];
#pragma unroll
                for (int j = 0; j < 3; j++) {
                    ull bb = bd[kg * 4 + j];
                    acc[j][0][0] = bb; acc[j][0][1] = bb;
                    acc[j][1][0] = bb; acc[j][1][1] = bb;
                }

                const ull* wk = wd + kg * 4;
                ull A[7], B[7];
                load_row(spair, pqy,     pqx, A);
                load_row(spair, pqy + 1, pqx, B);
                conv_step(wk,          A, B, acc);
                load_row(spair, pqy + 2, pqx, A);
                conv_step(wk + 60,     B, A, acc);
                load_row(spair, pqy + 3, pqx, B);
                conv_step(wk + 120,    A, B, acc);
                load_row(spair, pqy + 4, pqx, A);
                conv_step(wk + 180,    B, A, acc);
                load_row(spair, pqy + 5, pqx, B);
                conv_step(wk + 240,    A, B, acc);

#pragma unroll
                for (int j = 0; j < 3; j++) {
                    oacc[0][0] = fma2(acc[j][0][0], xq[0][j],     oacc[0][0]);
                    oacc[0][1] = fma2(acc[j][0][1], xq[0][j + 2], oacc[0][1]);
                    oacc[1][0] = fma2(acc[j][1][0], xq[1][j],     oacc[1][0]);
                    oacc[1][1] = fma2(acc[j][1][1], xq[1][j + 2], oacc[1][1]);
                }
            }
        }
    }

    float* ob = out + ((size_t)b * NC + o) * N * N;
#pragma unroll
    for (int sy = 0; sy < 2; sy++) {
#pragma unroll
        for (int cp = 0; cp < 2; cp++) {
            float lo, hi;
            upk(oacc[sy][cp], lo, hi);
            int row = ty0 + pqy + sy, col = tx0 + pqx + 2 * cp;
            if (row > 0 && row < N - 1) {
                if (col > 0 && col < N - 1)         ob[row * N + col]     = elu_f(lo);
                if (col + 1 > 0 && col + 1 < N - 1) ob[row * N + col + 1] = elu_f(hi);
            }
        }
    }
}

// ---------------------------------------------------------------------------
// fused two-level downsample: out1 = 2x2 mean (N/2), out2 = 4x4 mean (N/4).
// ---------------------------------------------------------------------------
__global__ void down2_kernel(const float* __restrict__ in,
                             float* __restrict__ out1, float* __restrict__ out2,
                             int C, int N)
{
    int idx = blockIdx.x * blockDim.x + threadIdx.x;
    const int N1 = N / 2, N2 = N / 4;
    const int total1 = C * N1 * N1;
    const int total2 = C * N2 * N2;
    if (idx < total1) {
        int c = idx / (N1 * N1);
        int p = idx % (N1 * N1);
        int h = p / N1, w = p % N1;
        const float* ib = in + (size_t)c * N * N;
        float sv = ib[(2 * h) * N + 2 * w] + ib[(2 * h) * N + 2 * w + 1]
                 + ib[(2 * h + 1) * N + 2 * w] + ib[(2 * h + 1) * N + 2 * w + 1];
        out1[idx] = 0.25f * sv;
    } else if (idx < total1 + total2) {
        int j = idx - total1;
        int c = j / (N2 * N2);
        int p = j % (N2 * N2);
        int h = p / N2, w = p % N2;
        const float* ib = in + (size_t)c * N * N;
        float sv = 0.f;
#pragma unroll
        for (int dy = 0; dy < 4; dy++)
#pragma unroll
            for (int dx = 0; dx < 4; dx++)
                sv += ib[(4 * h + dy) * N + 4 * w + dx];
        out2[j] = 0.0625f * sv;
    }
}

__global__ void combine_kernel(const float* __restrict__ x0,
                               const float* __restrict__ x1,
                               const float* __restrict__ x2,
                               const float* __restrict__ w5, const float* __restrict__ b5,
                               const float* __restrict__ w6, const float* __restrict__ b6,
                               float* __restrict__ out)
{
    int idx = blockIdx.x * blockDim.x + threadIdx.x;
    if (idx >= 8 * 128 * 128) return;
    int b = idx / (128 * 128);
    int p = idx % (128 * 128);
    int h = p / 128, w = p % 128;
    float v[NC];
#pragma unroll
    for (int c = 0; c < NC; c++) {
        v[c] = x0[((size_t)b * NC + c) * 16384 + p]
             + x1[((size_t)b * NC + c) * 4096 + (h >> 1) * 64 + (w >> 1)]
             + x2[((size_t)b * NC + c) * 1024 + (h >> 2) * 32 + (w >> 2)];
    }
    float accv = b6[0];
#pragma unroll
    for (int o = 0; o < NC; o++) {
        float y = b5[o];
#pragma unroll
        for (int c = 0; c < NC; c++) y += w5[o * NC + c] * v[c];
        y = elu_f(y);
        accv += w6[o] * y;
    }
    out[idx] = accv;
}

// ---------------------------------------------------------------------------
extern "C" void kernel_launch(void* const* d_in, const int* in_sizes, int n_in,
                              void* d_out, int out_size)
{
    const float* image = (const float*)d_in[0];
    const float* x_in  = (const float*)d_in[1];
    const float* iW1   = (const float*)d_in[2];
    const float* ib1   = (const float*)d_in[3];
    const float* iW2   = (const float*)d_in[4];
    const float* ib2   = (const float*)d_in[5];
    const float* bW1   = (const float*)d_in[6];
    const float* bb1   = (const float*)d_in[7];
    const float* bW2   = (const float*)d_in[8];
    const float* bb2   = (const float*)d_in[9];
    const float* w5    = (const float*)d_in[10];
    const float* b5    = (const float*)d_in[11];
    const float* w6    = (const float*)d_in[12];
    const float* b6    = (const float*)d_in[13];

    float* base;
    cudaGetSymbolAddress((void**)&base, g_buf);
    float* img1 = base;                        // 32768
    float* img2 = img1 + 32768;                // 8192
    float* x0a  = img2 + 8192;
    float* x0b  = x0a + 1048576;
    float* x1a  = x0b + 1048576;
    float* x1b  = x1a + 262144;
    float* x2a  = x1b + 262144;
    float* x2b  = x2a + 65536;
    float* tabW5 = x2b + 65536;                // 13*129600
    float* tabB  = tabW5 + 13 * 129600;        // 13*5184
    ull*   tabDup  = (ull*)(tabB + 13 * 5184); // 13*19200 ull
    ull*   tabBDup = tabDup + 13 * 19200;      // 13*768 ull

    cudaFuncSetAttribute(smmain_kernel,
                         cudaFuncAttributeMaxDynamicSharedMemorySize, 45120);

    // all tables upfront (x-independent)
    compose_kernel<<<(13 * 5184 + 127) / 128, 128>>>(
        iW1, ib1, iW2, ib2, bW1, bb1, bW2, bb2, tabW5, tabB, tabDup, tabBDup);

    // image pyramid: both levels in ONE launch (img2 = 4x4 mean of image)
    down2_kernel<<<(8 * 4096 + 8 * 1024 + 255) / 256, 256>>>(image, img1, img2, 8, 128);

    // init block (slot 0, nc_in=1, full-res only) with fused border
    smmain_kernel<<<dim3(20, 8, 8), 128, 45120>>>(image, img1, img2,
        x_in, x_in, x_in, x0a, x0a, x0a, tabDup, tabBDup, tabW5, tabB, 1, 0, 0);

    // downsample x: both levels in ONE launch (x2a = 4x4 mean of x0a)
    down2_kernel<<<(64 * 4096 + 64 * 1024 + 255) / 256, 256>>>(x0a, x1a, x2a, 64, 128);

    float *xc = x0a, *xn = x0b;
    float *x1c = x1a, *x1n = x1b;
    float *x2c = x2a, *x2n = x2b;

    for (int t = 0; t < 4; t++) {
        smmain_kernel<<<dim3(28, 8, 8), 128, 45120>>>(image, img1, img2,
            xc, x1c, x2c, xn, x1n, x2n, tabDup, tabBDup, tabW5, tabB,
            8, 1 + 3 * t, 1);
        { float* tp = xc;  xc = xn;   xn = tp; }
        { float* tp = x1c; x1c = x1n; x1n = tp; }
        { float* tp = x2c; x2c = x2n; x2n = tp; }
    }

    combine_kernel<<<(8 * 128 * 128 + 255) / 256, 256>>>(
        xc, x1c, x2c, w5, b5, w6, b6, (float*)d_out);
}

// round 17
// speedup vs baseline: 1.6153x; 1.0095x over previous
#include <cuda_runtime.h>
#include <math.h>

// ---------------------------------------------------------------------------
// SMModel — composed-5x5, packed f32x2. Hot path byte-identical to the
// measured optimum. Delta: border threads handle 2 pixels -> fewer border
// blocks -> grids drop below wave boundaries (1792->1600: 4->3 waves;
// 1280->1152: 3->2 waves at 592 concurrent blocks).
// ---------------------------------------------------------------------------

#define NC    8
#define HID   20
#define CHG   4

typedef unsigned long long ull;

__device__ __align__(16) float g_buf[5064832];

__device__ __forceinline__ float elu_f(float v) {
    return v > 0.f ? v : (expf(v) - 1.f);
}
__device__ __forceinline__ ull pk(float lo, float hi) {
    ull r; asm("mov.b64 %0, {%1, %2};" : "=l"(r) : "f"(lo), "f"(hi)); return r;
}
__device__ __forceinline__ void upk(ull v, float& lo, float& hi) {
    asm("mov.b64 {%0, %1}, %2;" : "=f"(lo), "=f"(hi) : "l"(v));
}
__device__ __forceinline__ ull fma2(ull a, ull b, ull c) {
    ull d; asm("fma.rn.f32x2 %0, %1, %2, %3;" : "=l"(d) : "l"(a), "l"(b), "l"(c)); return d;
}

// ---------------------------------------------------------------------------
// compose: ALL 13 layers, one launch.
// ---------------------------------------------------------------------------
__global__ void compose_kernel(
    const float* __restrict__ iW1, const float* __restrict__ ib1,
    const float* __restrict__ iW2, const float* __restrict__ ib2,
    const float* __restrict__ bW1, const float* __restrict__ bb1,
    const float* __restrict__ bW2, const float* __restrict__ bb2,
    float* __restrict__ tabW5, float* __restrict__ tabB,
    ull* __restrict__ tabDup, ull* __restrict__ tabBDup)
{
    int idx = blockIdx.x * blockDim.x + threadIdx.x;
    if (idx >= 13 * 5184) return;
    int l = idx / 5184;
    int r0 = idx % 5184;
    int cls = r0 / 576;
    int g = (r0 % 576) / 9, k = r0 % 9;
    if (l == 0 && g >= 8) return;

    const float *W1, *b1, *W2, *b2;
    if (l == 0) { W1 = iW1; b1 = ib1; W2 = iW2; b2 = ib2; }
    else {
        int m = l - 1;
        W1 = bW1 + (size_t)m * 1280 * 9;  b1 = bb1 + (size_t)m * 1280;
        W2 = bW2 + (size_t)m * 576 * 180; b2 = bb2 + (size_t)m * 576;
    }

    float T[25];
#pragma unroll
    for (int j = 0; j < 25; j++) T[j] = 0.f;
    float bias = b2[g * 9 + k];

    for (int q = 0; q < 9; q++) {
        int qy = q / 3 - 1, qx = q % 3 - 1;
        bool vyl = (qy >= 0), vyh = (qy <= 0), vxl = (qx >= 0), vxh = (qx <= 0);
        bool in;
        switch (cls) {
            case 0: in = true; break;
            case 1: in = vyl; break;
            case 2: in = vyh; break;
            case 3: in = vxl; break;
            case 4: in = vxh; break;
            case 5: in = vyl && vxl; break;
            case 6: in = vyl && vxh; break;
            case 7: in = vyh && vxl; break;
            default: in = vyh && vxh; break;
        }
        if (!in) continue;
        for (int c = 0; c < HID; c++) {
            float w2 = W2[((size_t)(g * 9 + k) * HID + c) * 9 + q];
            bias += b1[g * HID + c] * w2;
#pragma unroll
            for (int r = 0; r < 9; r++) {
                int ry = r / 3 - 1, rx = r % 3 - 1;
                T[(qy + ry + 2) * 5 + (qx + rx + 2)] += w2 * W1[(size_t)(g * HID + c) * 9 + r];
            }
        }
    }

    float* To = tabW5 + (size_t)l * 129600 + ((size_t)(cls * 64 + g) * 9 + k) * 25;
#pragma unroll
    for (int j = 0; j < 25; j++) To[j] = T[j];
    tabB[(size_t)l * 5184 + (size_t)(cls * 64 + g) * 9 + k] = bias;

    if (cls == 0) {
        ull* dd = tabDup + (size_t)l * 19200 + (size_t)g * 300;
        int kg = k / 3, j = k % 3;
#pragma unroll
        for (int d = 0; d < 25; d++) dd[d * 12 + kg * 4 + j] = pk(T[d], T[d]);
        tabBDup[(size_t)l * 768 + g * 12 + kg * 4 + j] = pk(bias, bias);
    }
}

// ---------------------------------------------------------------------------
__device__ __forceinline__ void load_row(const ull* __restrict__ spair,
                                         int row, int pqx, ull (&R)[7])
{
    const ull* base = spair + row * 36 + pqx;
    ulonglong2 t0 = *reinterpret_cast<const ulonglong2*>(base);
    ulonglong2 t1 = *reinterpret_cast<const ulonglong2*>(base + 2);
    ulonglong2 t2 = *reinterpret_cast<const ulonglong2*>(base + 4);
    R[0] = t0.x; R[1] = t0.y; R[2] = t1.x; R[3] = t1.y;
    R[4] = t2.x; R[5] = t2.y; R[6] = base[6];
}

__device__ __forceinline__ void conv_step(const ull* __restrict__ wrow,
                                          const ull (&R)[7], const ull (&S)[7],
                                          ull (&acc)[3][2][2])
{
#pragma unroll
    for (int dx = 0; dx < 5; dx++) {
        const ull* wp = wrow + dx * 12;
        ulonglong2 t = *reinterpret_cast<const ulonglong2*>(wp);
        ull w0 = t.x, w1 = t.y, w2 = wp[2];
        acc[0][0][0] = fma2(R[dx],     w0, acc[0][0][0]);
        acc[0][0][1] = fma2(R[dx + 2], w0, acc[0][0][1]);
        acc[0][1][0] = fma2(S[dx],     w0, acc[0][1][0]);
        acc[0][1][1] = fma2(S[dx + 2], w0, acc[0][1][1]);
        acc[1][0][0] = fma2(R[dx],     w1, acc[1][0][0]);
        acc[1][0][1] = fma2(R[dx + 2], w1, acc[1][0][1]);
        acc[1][1][0] = fma2(S[dx],     w1, acc[1][1][0]);
        acc[1][1][1] = fma2(S[dx + 2], w1, acc[1][1][1]);
        acc[2][0][0] = fma2(R[dx],     w2, acc[2][0][0]);
        acc[2][0][1] = fma2(R[dx + 2], w2, acc[2][0][1]);
        acc[2][1][0] = fma2(S[dx],     w2, acc[2][1][0]);
        acc[2][1][1] = fma2(S[dx + 2], w2, acc[2][1][1]);
    }
}

// ---------------------------------------------------------------------------
// main + border fused; dynamic smem 45120 B. Border threads do 2 pixels.
// mode0: 16 main + 2 border = 18; mode1: 21 main + 4 border = 25.
// ---------------------------------------------------------------------------
__global__ __launch_bounds__(128) void smmain_kernel(
    const float* __restrict__ img0, const float* __restrict__ img1p, const float* __restrict__ img2p,
    const float* __restrict__ xin0, const float* __restrict__ xin1, const float* __restrict__ xin2,
    float* __restrict__ out0, float* __restrict__ out1, float* __restrict__ out2,
    const ull* __restrict__ tabDup, const ull* __restrict__ tabBDup,
    const float* __restrict__ tabW5, const float* __restrict__ tabB,
    int nc_in, int slotBase, int mode)
{
    const int bx = blockIdx.x;
    const int o = blockIdx.y, b = blockIdx.z;
    const int tid = threadIdx.x;
    const int mainX = (mode == 0) ? 16 : 21;

    if (bx >= mainX) {
        // ---------------- border path (2 pixels per thread) ----------------
        int limit = (mode == 0) ? 508 : 884;
        for (int rep = 0; rep < 2; rep++) {
            int bp = ((bx - mainX) * 2 + rep) * 128 + tid;
            if (bp >= limit) return;
            int s, e;
            if (bp < 508)      { s = 0; e = bp; }
            else if (bp < 760) { s = 1; e = bp - 508; }
            else               { s = 2; e = bp - 760; }
            const float* img = (s == 0) ? img0 : (s == 1) ? img1p : img2p;
            const float* xin = (s == 0) ? xin0 : (s == 1) ? xin1 : xin2;
            float* out = (s == 0) ? out0 : (s == 1) ? out1 : out2;
            const int N = 128 >> s;
            const int slot = slotBase + s;

            int py, px;
            if (e < N)              { py = 0;     px = e; }
            else if (e < 2 * N)     { py = N - 1; px = e - N; }
            else if (e < 3 * N - 2) { py = e - 2 * N + 1;       px = 0; }
            else                    { py = e - (3 * N - 2) + 1; px = N - 1; }

            bool Tt = (py == 0), Bb = (py == N - 1), Ll = (px == 0), Rr = (px == N - 1);
            int cls = Tt ? (Ll ? 5 : (Rr ? 6 : 1))
                         : (Bb ? (Ll ? 7 : (Rr ? 8 : 2)) : (Ll ? 3 : 4));

            float w[25];
            const float* ibp = img + (size_t)b * N * N;
#pragma unroll
            for (int dy = 0; dy < 5; dy++)
#pragma unroll
                for (int dx = 0; dx < 5; dx++) {
                    int iy = py - 2 + dy, ix = px - 2 + dx;
                    w[dy * 5 + dx] = (iy >= 0 && iy < N && ix >= 0 && ix < N) ? ibp[iy * N + ix] : 0.f;
                }

            float accv = 0.f;
            for (int i = 0; i < nc_in; i++) {
                int g = o * nc_in + i;
                const float* tb = tabW5 + (size_t)slot * 129600 + ((size_t)(cls * 64 + g) * 9) * 25;
                const float* bb = tabB + (size_t)slot * 5184 + (size_t)(cls * 64 + g) * 9;
                const float* xb = xin + ((size_t)b * nc_in + i) * N * N;
                float Kf[9];
#pragma unroll
                for (int k = 0; k < 9; k++) Kf[k] = bb[k];
#pragma unroll
                for (int j = 0; j < 25; j++) {
                    float v = w[j];
#pragma unroll
                    for (int k = 0; k < 9; k++) Kf[k] += tb[k * 25 + j] * v;
                }
#pragma unroll
                for (int k = 0; k < 9; k++) {
                    int yy = py + k / 3 - 1, xx = px + k % 3 - 1;
                    float xv = (yy >= 0 && yy < N && xx >= 0 && xx < N) ? xb[yy * N + xx] : 0.f;
                    accv += Kf[k] * xv;
                }
            }
            out[((size_t)b * NC + o) * N * N + py * N + px] = elu_f(accv);
        }
        return;
    }

    // ---------------- main (interior) path — byte-identical hot code ------
    extern __shared__ __align__(16) char smraw[];
    float* simg  = (float*)smraw;                 // 36*36 f        = 5184 B
    ull*   spair = (ull*)(smraw + 5184);          // 36*36 ull      = 10368 B
    float* sxs   = (float*)(smraw + 15552);       // 4 * 34*36 f    = 19584 B
    ull*   sWd   = (ull*)(smraw + 35136);         // 4 * 300 ull    = 9600 B
    ull*   sBd   = (ull*)(smraw + 44736);         // 4 * 12 ull     = 384 B

    int s, tile;
    const float *img, *xin;
    float* out;
    if (bx < 16)      { s = 0; tile = bx;      img = img0;  xin = xin0; out = out0; }
    else if (bx < 20) { s = 1; tile = bx - 16; img = img1p; xin = xin1; out = out1; }
    else              { s = 2; tile = bx - 20; img = img2p; xin = xin2; out = out2; }
    const int N = 128 >> s;
    const int tilesX = N / 32;
    const int tx0 = (tile % tilesX) * 32, ty0 = (tile / tilesX) * 32;
    const int slot = slotBase + s;
    const int pqx = (tid & 7) * 4;
    const int pqy = (tid >> 3) * 2;

    const float* ib = img + (size_t)b * N * N;
    for (int idx = tid; idx < 36 * 36; idx += 128) {
        int ly = idx / 36, lx = idx % 36;
        int gy = ty0 - 2 + ly, gx = tx0 - 2 + lx;
        simg[idx] = (gy >= 0 && gy < N && gx >= 0 && gx < N) ? ib[gy * N + gx] : 0.f;
    }
    __syncthreads();
    for (int idx = tid; idx < 36 * 35; idx += 128) {
        int ly = idx / 35, lx = idx % 35;
        spair[ly * 36 + lx] = pk(simg[ly * 36 + lx], simg[ly * 36 + lx + 1]);
    }
    // (sync before compute provided by the per-phase post-load barrier)

    ull oacc[2][2];
    oacc[0][0] = 0ull; oacc[0][1] = 0ull; oacc[1][0] = 0ull; oacc[1][1] = 0ull;

    for (int i0 = 0; i0 < nc_in; i0 += CHG) {
        const int chg = (nc_in - i0 < CHG) ? (nc_in - i0) : CHG;
        __syncthreads();   // previous phase compute done

        for (int idx = tid; idx < chg * 1156; idx += 128) {
            int ci = idx / 1156, r = idx % 1156;
            int ly = r / 34, lx = r % 34;
            int gy = ty0 - 1 + ly, gx = tx0 - 1 + lx;
            const float* xb = xin + ((size_t)b * nc_in + (i0 + ci)) * N * N;
            sxs[ci * 1224 + ly * 36 + lx] =
                (gy >= 0 && gy < N && gx >= 0 && gx < N) ? xb[gy * N + gx] : 0.f;
        }
        for (int idx = tid; idx < chg * 300; idx += 128) {
            int ci = idx / 300, j = idx % 300;
            int g = o * nc_in + i0 + ci;
            sWd[ci * 300 + j] = tabDup[(size_t)slot * 19200 + (size_t)g * 300 + j];
        }
        if (tid < chg * 12) {
            int ci = tid / 12, j = tid % 12;
            int g = o * nc_in + i0 + ci;
            sBd[ci * 12 + j] = tabBDup[(size_t)slot * 768 + (size_t)g * 12 + j];
        }
        __syncthreads();

#pragma unroll 1
        for (int ci = 0; ci < chg; ci++) {
            const ull*   wd = sWd + ci * 300;
            const ull*   bd = sBd + ci * 12;
            const float* xc = sxs + ci * 1224;

#pragma unroll 1
            for (int kg = 0; kg < 3; kg++) {
                ull xq[2][5];
#pragma unroll
                for (int rr = 0; rr < 2; rr++) {
                    const float* xr = xc + (pqy + kg + rr) * 36 + pqx;
                    float4 q4 = *reinterpret_cast<const float4*>(xr);
                    float2 q2 = *reinterpret_cast<const float2*>(xr + 4);
                    xq[rr][0] = pk(q4.x, q4.y); xq[rr][1] = pk(q4.y, q4.z);
                    xq[rr][2] = pk(q4.z, q4.w); xq[rr][3] = pk(q4.w, q2.x);
                    xq[rr][4] = pk(q2.x, q2.y);
                }

                ull acc[3][2][2];
#pragma unroll
                for (int j = 0; j < 3; j++) {
                    ull bb = bd[kg * 4 + j];
                    acc[j][0][0] = bb; acc[j][0][1] = bb;
                    acc[j][1][0] = bb; acc[j][1][1] = bb;
                }

                const ull* wk = wd + kg * 4;
                ull A[7], B[7];
                load_row(spair, pqy,     pqx, A);
                load_row(spair, pqy + 1, pqx, B);
                conv_step(wk,          A, B, acc);
                load_row(spair, pqy + 2, pqx, A);
                conv_step(wk + 60,     B, A, acc);
                load_row(spair, pqy + 3, pqx, B);
                conv_step(wk + 120,    A, B, acc);
                load_row(spair, pqy + 4, pqx, A);
                conv_step(wk + 180,    B, A, acc);
                load_row(spair, pqy + 5, pqx, B);
                conv_step(wk + 240,    A, B, acc);

#pragma unroll
                for (int j = 0; j < 3; j++) {
                    oacc[0][0] = fma2(acc[j][0][0], xq[0][j],     oacc[0][0]);
                    oacc[0][1] = fma2(acc[j][0][1], xq[0][j + 2], oacc[0][1]);
                    oacc[1][0] = fma2(acc[j][1][0], xq[1][j],     oacc[1][0]);
                    oacc[1][1] = fma2(acc[j][1][1], xq[1][j + 2], oacc[1][1]);
                }
            }
        }
    }

    float* ob = out + ((size_t)b * NC + o) * N * N;
#pragma unroll
    for (int sy = 0; sy < 2; sy++) {
#pragma unroll
        for (int cp = 0; cp < 2; cp++) {
            float lo, hi;
            upk(oacc[sy][cp], lo, hi);
            int row = ty0 + pqy + sy, col = tx0 + pqx + 2 * cp;
            if (row > 0 && row < N - 1) {
                if (col > 0 && col < N - 1)         ob[row * N + col]     = elu_f(lo);
                if (col + 1 > 0 && col + 1 < N - 1) ob[row * N + col + 1] = elu_f(hi);
            }
        }
    }
}

// ---------------------------------------------------------------------------
// fused two-level downsample: out1 = 2x2 mean (N/2), out2 = 4x4 mean (N/4).
// ---------------------------------------------------------------------------
__global__ void down2_kernel(const float* __restrict__ in,
                             float* __restrict__ out1, float* __restrict__ out2,
                             int C, int N)
{
    int idx = blockIdx.x * blockDim.x + threadIdx.x;
    const int N1 = N / 2, N2 = N / 4;
    const int total1 = C * N1 * N1;
    const int total2 = C * N2 * N2;
    if (idx < total1) {
        int c = idx / (N1 * N1);
        int p = idx % (N1 * N1);
        int h = p / N1, w = p % N1;
        const float* ib = in + (size_t)c * N * N;
        float sv = ib[(2 * h) * N + 2 * w] + ib[(2 * h) * N + 2 * w + 1]
                 + ib[(2 * h + 1) * N + 2 * w] + ib[(2 * h + 1) * N + 2 * w + 1];
        out1[idx] = 0.25f * sv;
    } else if (idx < total1 + total2) {
        int j = idx - total1;
        int c = j / (N2 * N2);
        int p = j % (N2 * N2);
        int h = p / N2, w = p % N2;
        const float* ib = in + (size_t)c * N * N;
        float sv = 0.f;
#pragma unroll
        for (int dy = 0; dy < 4; dy++)
#pragma unroll
            for (int dx = 0; dx < 4; dx++)
                sv += ib[(4 * h + dy) * N + 4 * w + dx];
        out2[j] = 0.0625f * sv;
    }
}

__global__ void combine_kernel(const float* __restrict__ x0,
                               const float* __restrict__ x1,
                               const float* __restrict__ x2,
                               const float* __restrict__ w5, const float* __restrict__ b5,
                               const float* __restrict__ w6, const float* __restrict__ b6,
                               float* __restrict__ out)
{
    int idx = blockIdx.x * blockDim.x + threadIdx.x;
    if (idx >= 8 * 128 * 128) return;
    int b = idx / (128 * 128);
    int p = idx % (128 * 128);
    int h = p / 128, w = p % 128;
    float v[NC];
#pragma unroll
    for (int c = 0; c < NC; c++) {
        v[c] = x0[((size_t)b * NC + c) * 16384 + p]
             + x1[((size_t)b * NC + c) * 4096 + (h >> 1) * 64 + (w >> 1)]
             + x2[((size_t)b * NC + c) * 1024 + (h >> 2) * 32 + (w >> 2)];
    }
    float accv = b6[0];
#pragma unroll
    for (int o = 0; o < NC; o++) {
        float y = b5[o];
#pragma unroll
        for (int c = 0; c < NC; c++) y += w5[o * NC + c] * v[c];
        y = elu_f(y);
        accv += w6[o] * y;
    }
    out[idx] = accv;
}

// ---------------------------------------------------------------------------
extern "C" void kernel_launch(void* const* d_in, const int* in_sizes, int n_in,
                              void* d_out, int out_size)
{
    const float* image = (const float*)d_in[0];
    const float* x_in  = (const float*)d_in[1];
    const float* iW1   = (const float*)d_in[2];
    const float* ib1   = (const float*)d_in[3];
    const float* iW2   = (const float*)d_in[4];
    const float* ib2   = (const float*)d_in[5];
    const float* bW1   = (const float*)d_in[6];
    const float* bb1   = (const float*)d_in[7];
    const float* bW2   = (const float*)d_in[8];
    const float* bb2   = (const float*)d_in[9];
    const float* w5    = (const float*)d_in[10];
    const float* b5    = (const float*)d_in[11];
    const float* w6    = (const float*)d_in[12];
    const float* b6    = (const float*)d_in[13];

    float* base;
    cudaGetSymbolAddress((void**)&base, g_buf);
    float* img1 = base;
    float* img2 = img1 + 32768;
    float* x0a  = img2 + 8192;
    float* x0b  = x0a + 1048576;
    float* x1a  = x0b + 1048576;
    float* x1b  = x1a + 262144;
    float* x2a  = x1b + 262144;
    float* x2b  = x2a + 65536;
    float* tabW5 = x2b + 65536;                // 13*129600
    float* tabB  = tabW5 + 13 * 129600;        // 13*5184
    ull*   tabDup  = (ull*)(tabB + 13 * 5184); // 13*19200 ull
    ull*   tabBDup = tabDup + 13 * 19200;      // 13*768 ull

    cudaFuncSetAttribute(smmain_kernel,
                         cudaFuncAttributeMaxDynamicSharedMemorySize, 45120);

    // all tables upfront (x-independent)
    compose_kernel<<<(13 * 5184 + 127) / 128, 128>>>(
        iW1, ib1, iW2, ib2, bW1, bb1, bW2, bb2, tabW5, tabB, tabDup, tabBDup);

    // image pyramid: both levels in ONE launch
    down2_kernel<<<(8 * 4096 + 8 * 1024 + 255) / 256, 256>>>(image, img1, img2, 8, 128);

    // init block: 16 main + 2 border = 18 -> grid 1152 (2 waves at 592)
    smmain_kernel<<<dim3(18, 8, 8), 128, 45120>>>(image, img1, img2,
        x_in, x_in, x_in, x0a, x0a, x0a, tabDup, tabBDup, tabW5, tabB, 1, 0, 0);

    // downsample x: both levels in ONE launch
    down2_kernel<<<(64 * 4096 + 64 * 1024 + 255) / 256, 256>>>(x0a, x1a, x2a, 64, 128);

    float *xc = x0a, *xn = x0b;
    float *x1c = x1a, *x1n = x1b;
    float *x2c = x2a, *x2n = x2b;

    for (int t = 0; t < 4; t++) {
        // 21 main + 4 border = 25 -> grid 1600 (3 waves, was 4)
        smmain_kernel<<<dim3(25, 8, 8), 128, 45120>>>(image, img1, img2,
            xc, x1c, x2c, xn, x1n, x2n, tabDup, tabBDup, tabW5, tabB,
            8, 1 + 3 * t, 1);
        { float* tp = xc;  xc = xn;   xn = tp; }
        { float* tp = x1c; x1c = x1n; x1n = tp; }
        { float* tp = x2c; x2c = x2n; x2n = tp; }
    }

    combine_kernel<<<(8 * 128 * 128 + 255) / 256, 256>>>(
        xc, x1c, x2c, w5, b5, w6, b6, (float*)d_out);
}